// round 6
// baseline (speedup 1.0000x reference)
#include <cuda_runtime.h>
#include <cuda_bf16.h>
#include <cstdint>
#include <cstddef>

#define NI 64
#define NH 32
#define HW 16384

__device__ float d_c[128];
__device__ float d_s[128];

__device__ float s_xan [NI*HW];
__device__ float s_F1  [NI*128*33*2];
__device__ float s_F2  [NI*64*33*2];
__device__ float s_rtmp[NI*64*33*2];
__device__ float s_R64 [NI*64*64];
__device__ float s_t64 [(size_t)NI*NH*64*16*2];
__device__ float s_t128[(size_t)NI*NH*128*16*2];
__device__ float s_k   [(size_t)NI*NH*64*64];
__device__ float s_q   [(size_t)NI*NH*64*64];
__device__ float s_v   [(size_t)NI*NH*128*128];
__device__ float s_attn[64*1024];
__device__ float s_out [(size_t)NI*NH*128*128];
__device__ float s_G1  [(size_t)NI*NH*128*32*2];
__device__ float s_G2  [(size_t)NI*NH*64*32*2];
__device__ float s_PF  [NI*64*32*2];
__device__ float s_ptmp[NI*128*32*2];
__device__ float s_fno [NI*HW];
__device__ float s_att [NI*HW];
__device__ float s_an  [NI*HW];
__device__ float s_m   [NI*HW];
__device__ float s_MF1 [NI*128*32*2];
__device__ float s_MF2 [NI*64*32*2];
__device__ float s_MF  [NI*64*32*2];

__device__ __forceinline__ void load_tables(float* cs, float* ss) {
    for (int t = threadIdx.x; t < 128; t += blockDim.x) { cs[t] = d_c[t]; ss[t] = d_s[t]; }
}

__global__ void k_init() {
    int k = threadIdx.x;
    d_c[k] = cospif(k / 64.0f);
    d_s[k] = sinpif(k / 64.0f);
}

// instance norm over 16384 elems per image; optional pre-add and post-add
__global__ void k_inorm(const float* __restrict__ src, const float* __restrict__ add,
                        float* __restrict__ dst, const float* __restrict__ gA,
                        const float* __restrict__ bA, int gi, const float* __restrict__ post) {
    int img = blockIdx.x, tid = threadIdx.x;
    const float* s = src + (size_t)img * HW;
    const float* a = add ? add + (size_t)img * HW : nullptr;
    float sum = 0.f, sq = 0.f;
    for (int p = tid; p < HW; p += 256) {
        float v = s[p]; if (a) v += a[p];
        sum += v; sq += v * v;
    }
    __shared__ float r1[256], r2[256];
    r1[tid] = sum; r2[tid] = sq; __syncthreads();
    for (int st = 128; st > 0; st >>= 1) {
        if (tid < st) { r1[tid] += r1[tid + st]; r2[tid] += r2[tid + st]; }
        __syncthreads();
    }
    __shared__ float mean_s, istd_s;
    if (tid == 0) {
        float m = r1[0] * (1.f / HW);
        float var = r2[0] * (1.f / HW) - m * m;
        mean_s = m; istd_s = rsqrtf(var + 1e-5f);
    }
    __syncthreads();
    float g = gA[gi], bb = bA[gi], m = mean_s, is = istd_s;
    for (int p = tid; p < HW; p += 256) {
        float v = s[p]; if (a) v += a[p];
        float r = (v - m) * is * g + bb;
        if (post) r += post[(size_t)img * HW + p];
        dst[(size_t)img * HW + p] = r;
    }
}

// fwd partial DFT stage1 (cols): F1[n,h,c] = (1/128) sum_w x e^{-2pi i c w/128}
template <int NC>
__global__ void k_fwd1(const float* __restrict__ x, float* __restrict__ out) {
    int n = blockIdx.x, hb = blockIdx.y;
    __shared__ float xs[8 * 128];
    __shared__ float cs[128], ss[128];
    load_tables(cs, ss);
    for (int t = threadIdx.x; t < 8 * 128; t += blockDim.x)
        xs[t] = x[((size_t)n * 128 + hb * 8) * 128 + t];
    __syncthreads();
    int t = threadIdx.x;
    if (t >= 8 * NC) return;
    int hl = t / NC, c = t % NC;
    float re = 0.f, im = 0.f;
    int idx = 0;
    #pragma unroll 4
    for (int w = 0; w < 128; w++) {
        float v = xs[hl * 128 + w];
        re += v * cs[idx]; im -= v * ss[idx];
        idx = (idx + c) & 127;
    }
    int h = hb * 8 + hl;
    size_t o = ((size_t)(n * 128 + h) * NC + c) * 2;
    out[o] = re * (1.f / 128.f); out[o + 1] = im * (1.f / 128.f);
}

// fwd stage2 (rows): 64 mode rows, jr<32 -> r=jr else r=jr+64
__global__ void k_fwd2(const float* __restrict__ F1, float* __restrict__ F2o, int NC) {
    int n = blockIdx.x;
    __shared__ float fs[128 * 33 * 2];
    __shared__ float cs[128], ss[128];
    load_tables(cs, ss);
    int tot = 128 * NC * 2;
    for (int t = threadIdx.x; t < tot; t += blockDim.x)
        fs[t] = F1[(size_t)n * tot + t];
    __syncthreads();
    for (int o = threadIdx.x; o < 64 * NC; o += blockDim.x) {
        int jr = o / NC, c = o % NC;
        int r = jr < 32 ? jr : jr + 64;
        float re = 0.f, im = 0.f;
        int idx = 0;
        #pragma unroll 4
        for (int h = 0; h < 128; h++) {
            float ar = fs[(h * NC + c) * 2], ai = fs[(h * NC + c) * 2 + 1];
            float tc = cs[idx], ts = ss[idx];       // e^{-i t}
            re += ar * tc + ai * ts;
            im += ai * tc - ar * ts;
            idx = (idx + r) & 127;
        }
        size_t oo = ((size_t)(n * 64 + jr) * NC + c) * 2;
        F2o[oo] = re * (1.f / 128.f); F2o[oo + 1] = im * (1.f / 128.f);
    }
}

// row inverse (complex ifft, unnormalized): bins jr<32->jr else jr+(P-64)
__global__ void k_invrow(const float* __restrict__ src, float* __restrict__ dst, int NC, int P) {
    int n = blockIdx.x;
    __shared__ float fs[64 * 33 * 2];
    __shared__ float cs[128], ss[128];
    load_tables(cs, ss);
    int tot = 64 * NC * 2;
    for (int t = threadIdx.x; t < tot; t += blockDim.x)
        fs[t] = src[(size_t)n * tot + t];
    __syncthreads();
    int step = 128 / P;
    for (int o = threadIdx.x; o < P * NC; o += blockDim.x) {
        int y = o / NC, c = o % NC;
        float re = 0.f, im = 0.f;
        for (int jr = 0; jr < 64; jr++) {
            int bin = jr < 32 ? jr : jr + (P - 64);
            int idx = (bin * y * step) & 127;
            float ar = fs[(jr * NC + c) * 2], ai = fs[(jr * NC + c) * 2 + 1];
            float tc = cs[idx], ts = ss[idx];       // e^{+i t}
            re += ar * tc - ai * ts;
            im += ar * ts + ai * tc;
        }
        size_t oo = ((size_t)(n * P + y) * NC + c) * 2;
        dst[oo] = re; dst[oo + 1] = im;
    }
}

// c2r col inverse (unnormalized); Nyquist when (NC-1)*2==P
__global__ void k_invcol(const float* __restrict__ tmp, float* __restrict__ dst, int NC, int P) {
    int n = blockIdx.x;
    __shared__ float ts_[128 * 32 * 2];
    __shared__ float cs[128], ss[128];
    load_tables(cs, ss);
    int tot = P * NC * 2;
    for (int t = threadIdx.x; t < tot; t += blockDim.x)
        ts_[t] = tmp[(size_t)n * tot + t];
    __syncthreads();
    int nyq = ((NC - 1) * 2 == P) ? 1 : 0;
    int cmax = nyq ? NC - 1 : NC;
    int step = 128 / P;
    int PP = P * P;
    for (int p = threadIdx.x; p < PP; p += blockDim.x) {
        int y = p / P, x = p % P;
        const float* row = ts_ + y * NC * 2;
        float acc = row[0];
        for (int c = 1; c < cmax; c++) {
            int idx = (c * x * step) & 127;
            acc += 2.f * (row[2 * c] * cs[idx] - row[2 * c + 1] * ss[idx]);
        }
        if (nyq) {
            int idx = ((NC - 1) * x * step) & 127;
            acc += row[(NC - 1) * 2] * cs[idx];
        }
        dst[(size_t)n * PP + p] = acc;
    }
}

// K/Q/V: mode multiply + row inverse. modes jj<16: F2 row jj, sgn0, bin jj;
// jj>=16: F2 row jj+32 (orig 112..127), sgn1, bin jj+(P-32)
__global__ void k_invrow_kqv(const float* __restrict__ F2src, const float* __restrict__ w,
                             float* __restrict__ dst, int P) {
    int i = blockIdx.x, o = blockIdx.y;
    __shared__ float fw[32 * 16 * 2];
    __shared__ float cs[128], ss[128];
    load_tables(cs, ss);
    for (int t = threadIdx.x; t < 512; t += blockDim.x) {
        int jj = t >> 4, c = t & 15;
        int jr = jj < 16 ? jj : jj + 32;
        int sgn = jj < 16 ? 0 : 1, jjm = jj & 15;
        float ar = F2src[((size_t)(i * 64 + jr) * 33 + c) * 2];
        float ai = F2src[((size_t)(i * 64 + jr) * 33 + c) * 2 + 1];
        const float* wp = w + (((size_t)(sgn * 32 + o) * 16 + jjm) * 16 + c) * 2;
        float wr = wp[0], wi = wp[1];
        fw[t * 2]     = ar * wr - ai * wi;
        fw[t * 2 + 1] = ar * wi + ai * wr;
    }
    __syncthreads();
    int step = 128 / P;
    for (int t = threadIdx.x; t < P * 16; t += blockDim.x) {
        int y = t >> 4, c = t & 15;
        float re = 0.f, im = 0.f;
        #pragma unroll
        for (int jj = 0; jj < 32; jj++) {
            int bin = jj < 16 ? jj : jj + (P - 32);
            int idx = (bin * y * step) & 127;
            float ar = fw[(jj * 16 + c) * 2], ai = fw[(jj * 16 + c) * 2 + 1];
            re += ar * cs[idx] - ai * ss[idx];
            im += ar * ss[idx] + ai * cs[idx];
        }
        size_t oo = (((size_t)(i * 32 + o) * P + y) * 16 + c) * 2;
        dst[oo] = re; dst[oo + 1] = im;
    }
}

// K/Q/V c2r + fused per-head linear skip
__global__ void k_invcol_skip(const float* __restrict__ tmp, const float* __restrict__ skipsrc,
                              const float* __restrict__ ws, const float* __restrict__ bs,
                              float* __restrict__ dst, int P) {
    int img = blockIdx.x;
    int i = img >> 5, o = img & 31;
    __shared__ float ts_[128 * 16 * 2];
    __shared__ float cs[128], ss[128];
    load_tables(cs, ss);
    int tot = P * 32;
    for (int t = threadIdx.x; t < tot; t += blockDim.x)
        ts_[t] = tmp[(size_t)img * tot + t];
    __syncthreads();
    float wsv = ws[o], bsv = bs[o];
    int step = 128 / P;
    int PP = P * P;
    for (int p = threadIdx.x; p < PP; p += blockDim.x) {
        int y = p / P, x = p % P;
        const float* row = ts_ + y * 32;
        float acc = row[0];
        #pragma unroll
        for (int c = 1; c < 16; c++) {
            int idx = (c * x * step) & 127;
            acc += 2.f * (row[2 * c] * cs[idx] - row[2 * c + 1] * ss[idx]);
        }
        dst[(size_t)img * PP + p] = acc + wsv * skipsrc[(size_t)i * PP + p] + bsv;
    }
}

// scores + softmax fused: one block per (b,h); warp = one query row t
__global__ void k_scores(const float* __restrict__ q, const float* __restrict__ k,
                         float* __restrict__ attn) {
    int bh = blockIdx.x, b = bh >> 5, h = bh & 31;
    int tid = threadIdx.x, t = tid >> 5, s = tid & 31;
    __shared__ float qs_[32 * 65], ks_[32 * 65];
    float acc = 0.f;
    for (int kk = 0; kk < 4096; kk += 64) {
        __syncthreads();
        for (int idx = tid; idx < 2048; idx += 1024) {
            int row = idx >> 6, col = idx & 63;
            size_t base = (size_t)((b * 32 + row) * 32 + h) * 4096 + kk + col;
            qs_[row * 65 + col] = q[base];
            ks_[row * 65 + col] = k[base];
        }
        __syncthreads();
        #pragma unroll 8
        for (int j = 0; j < 64; j++)
            acc += qs_[t * 65 + j] * ks_[s * 65 + j];
    }
    acc *= (1.f / 64.f);
    float mx = acc;
    for (int o = 16; o > 0; o >>= 1) mx = fmaxf(mx, __shfl_xor_sync(0xffffffffu, mx, o));
    float e = expf(acc - mx), sm = e;
    for (int o = 16; o > 0; o >>= 1) sm += __shfl_xor_sync(0xffffffffu, sm, o);
    attn[bh * 1024 + tid] = e / sm;
}

// out = attn @ v (v read once)
__global__ void k_attnout(const float* __restrict__ attn, const float* __restrict__ v,
                          float* __restrict__ outimg) {
    int bh = blockIdx.x, b = bh >> 5, h = bh & 31;
    int pos = blockIdx.y * 256 + threadIdx.x;
    __shared__ float a_sh[1024];
    for (int t = threadIdx.x; t < 1024; t += 256) a_sh[t] = attn[bh * 1024 + t];
    __syncthreads();
    float acc[32];
    #pragma unroll
    for (int t = 0; t < 32; t++) acc[t] = 0.f;
    for (int s = 0; s < 32; s++) {
        float vv = v[((size_t)((b * 32 + s) * 32 + h) << 14) + pos];
        #pragma unroll
        for (int t = 0; t < 32; t++) acc[t] += a_sh[t * 32 + s] * vv;
    }
    #pragma unroll
    for (int t = 0; t < 32; t++)
        outimg[((size_t)((b * 32 + t) * 32 + h) << 14) + pos] = acc[t];
}

// proj: contract 32 channels in mode space
__global__ void k_projmodes(const float* __restrict__ G2, const float* __restrict__ w,
                            float* __restrict__ PF) {
    int i = blockIdx.x;
    for (int t = threadIdx.x; t < 64 * 32; t += blockDim.x) {
        int jj = t >> 5, c = t & 31;
        int sgn = jj < 32 ? 0 : 1, jjm = jj & 31;
        float re = 0.f, im = 0.f;
        for (int ch = 0; ch < 32; ch++) {
            const float* g = G2 + (((size_t)(i * 32 + ch) * 64 + jj) * 32 + c) * 2;
            const float* wp = w + (((size_t)(sgn * 32 + ch) * 32 + jjm) * 32 + c) * 2;
            float ar = g[0], ai = g[1], wr = wp[0], wi = wp[1];
            re += ar * wr - ai * wi;
            im += ar * wi + ai * wr;
        }
        size_t oo = ((size_t)(i * 64 + jj) * 32 + c) * 2;
        PF[oo] = re; PF[oo + 1] = im;
    }
}

__global__ void k_projskip(const float* __restrict__ outimg, const float* __restrict__ wPs,
                           const float* __restrict__ bPs, float* __restrict__ fno) {
    size_t id = (size_t)blockIdx.x * 256 + threadIdx.x;
    int i = (int)(id >> 14), p = (int)(id & 16383);
    float acc = bPs[0];
    for (int ch = 0; ch < 32; ch++)
        acc += wPs[ch] * outimg[(((size_t)i * 32 + ch) << 14) + p];
    fno[id] += acc;
}

__global__ void k_mixmodes(const float* __restrict__ F2m, const float* __restrict__ w,
                           float* __restrict__ MF) {
    int i = blockIdx.x;
    for (int t = threadIdx.x; t < 64 * 32; t += blockDim.x) {
        int jj = t >> 5, c = t & 31;
        int sgn = jj < 32 ? 0 : 1, jjm = jj & 31;
        const float* g = F2m + ((size_t)(i * 64 + jj) * 32 + c) * 2;
        const float* wp = w + (((size_t)sgn * 32 + jjm) * 32 + c) * 2;
        float ar = g[0], ai = g[1], wr = wp[0], wi = wp[1];
        size_t oo = ((size_t)(i * 64 + jj) * 32 + c) * 2;
        MF[oo] = ar * wr - ai * wi;
        MF[oo + 1] = ar * wi + ai * wr;
    }
}

__global__ void k_mixeps(float* __restrict__ dst, const float* __restrict__ fn,
                         const float* __restrict__ src, const float* __restrict__ ws,
                         const float* __restrict__ bs, int dogelu) {
    size_t id = (size_t)blockIdx.x * 256 + threadIdx.x;
    float v = fn[id] + ws[0] * src[id] + bs[0];
    if (dogelu) v = 0.5f * v * (1.f + erff(v * 0.70710678118654752f));
    dst[id] = v;
}

extern "C" void kernel_launch(void* const* d_in, const int* in_sizes, int n_in,
                              void* d_out, int out_size) {
    const float* x    = (const float*)d_in[0];
    const float* wK   = (const float*)d_in[1];
    const float* wKs  = (const float*)d_in[2];
    const float* bKs  = (const float*)d_in[3];
    const float* wQ   = (const float*)d_in[4];
    const float* wQs  = (const float*)d_in[5];
    const float* bQs  = (const float*)d_in[6];
    const float* wV   = (const float*)d_in[7];
    const float* wVs  = (const float*)d_in[8];
    const float* bVs  = (const float*)d_in[9];
    const float* wP   = (const float*)d_in[10];
    const float* wPs  = (const float*)d_in[11];
    const float* bPs  = (const float*)d_in[12];
    const float* wM0  = (const float*)d_in[13];
    const float* wM0s = (const float*)d_in[14];
    const float* bM0s = (const float*)d_in[15];
    const float* wM1  = (const float*)d_in[16];
    const float* wM1s = (const float*)d_in[17];
    const float* bM1s = (const float*)d_in[18];
    const float* ng   = (const float*)d_in[19];
    const float* nb   = (const float*)d_in[20];
    float* out = (float*)d_out;

    float *p_xan, *p_F1, *p_F2, *p_rtmp, *p_R64, *p_t64, *p_t128, *p_k, *p_q, *p_v;
    float *p_attn, *p_out, *p_G1, *p_G2, *p_PF, *p_ptmp, *p_fno, *p_att, *p_an;
    float *p_m, *p_MF1, *p_MF2, *p_MF;
    cudaGetSymbolAddress((void**)&p_xan,  s_xan);
    cudaGetSymbolAddress((void**)&p_F1,   s_F1);
    cudaGetSymbolAddress((void**)&p_F2,   s_F2);
    cudaGetSymbolAddress((void**)&p_rtmp, s_rtmp);
    cudaGetSymbolAddress((void**)&p_R64,  s_R64);
    cudaGetSymbolAddress((void**)&p_t64,  s_t64);
    cudaGetSymbolAddress((void**)&p_t128, s_t128);
    cudaGetSymbolAddress((void**)&p_k,    s_k);
    cudaGetSymbolAddress((void**)&p_q,    s_q);
    cudaGetSymbolAddress((void**)&p_v,    s_v);
    cudaGetSymbolAddress((void**)&p_attn, s_attn);
    cudaGetSymbolAddress((void**)&p_out,  s_out);
    cudaGetSymbolAddress((void**)&p_G1,   s_G1);
    cudaGetSymbolAddress((void**)&p_G2,   s_G2);
    cudaGetSymbolAddress((void**)&p_PF,   s_PF);
    cudaGetSymbolAddress((void**)&p_ptmp, s_ptmp);
    cudaGetSymbolAddress((void**)&p_fno,  s_fno);
    cudaGetSymbolAddress((void**)&p_att,  s_att);
    cudaGetSymbolAddress((void**)&p_an,   s_an);
    cudaGetSymbolAddress((void**)&p_m,    s_m);
    cudaGetSymbolAddress((void**)&p_MF1,  s_MF1);
    cudaGetSymbolAddress((void**)&p_MF2,  s_MF2);
    cudaGetSymbolAddress((void**)&p_MF,   s_MF);

    k_init<<<1, 128>>>();

    // xa_n = InstanceNorm(x) (idx0)
    k_inorm<<<NI, 256>>>(x, nullptr, p_xan, ng, nb, 0, nullptr);

    // forward partial DFT of xa_n (64 mode rows x 33 cols)
    k_fwd1<33><<<dim3(NI, 16), 264>>>(p_xan, p_F1);
    k_fwd2<<<NI, 256>>>(p_F1, p_F2, 33);

    // spectral resample of xa_n to 64x64 (shared K/Q skip)
    k_invrow<<<NI, 256>>>(p_F2, p_rtmp, 33, 64);
    k_invcol<<<NI, 256>>>(p_rtmp, p_R64, 33, 64);

    // K, Q (half res), V (full res)
    k_invrow_kqv<<<dim3(NI, NH), 256>>>(p_F2, wK, p_t64, 64);
    k_invcol_skip<<<NI * NH, 256>>>(p_t64, p_R64, wKs, bKs, p_k, 64);
    k_invrow_kqv<<<dim3(NI, NH), 256>>>(p_F2, wQ, p_t64, 64);
    k_invcol_skip<<<NI * NH, 256>>>(p_t64, p_R64, wQs, bQs, p_q, 64);
    k_invrow_kqv<<<dim3(NI, NH), 256>>>(p_F2, wV, p_t128, 128);
    k_invcol_skip<<<NI * NH, 256>>>(p_t128, p_xan, wVs, bVs, p_v, 128);

    // attention
    k_scores<<<64, 1024>>>(p_q, p_k, p_attn);
    k_attnout<<<dim3(64, 64), 256>>>(p_attn, p_v, p_out);

    // proj FNO layer
    k_fwd1<32><<<dim3(NI * NH, 16), 256>>>(p_out, p_G1);
    k_fwd2<<<NI * NH, 256>>>(p_G1, p_G2, 32);
    k_projmodes<<<NI, 256>>>(p_G2, wP, p_PF);
    k_invrow<<<NI, 256>>>(p_PF, p_ptmp, 32, 128);
    k_invcol<<<NI, 256>>>(p_ptmp, p_fno, 32, 128);
    k_projskip<<<NI * HW / 256, 256>>>(p_out, wPs, bPs, p_fno);

    // attention = IN(projd + xa) (idx1); an = IN(attention) (idx2)
    k_inorm<<<NI, 256>>>(p_fno, x, p_att, ng, nb, 1, nullptr);
    k_inorm<<<NI, 256>>>(p_att, nullptr, p_an, ng, nb, 2, nullptr);

    // mixer layer 0 (norm idx3 + gelu)
    k_fwd1<32><<<dim3(NI, 16), 256>>>(p_an, p_MF1);
    k_fwd2<<<NI, 256>>>(p_MF1, p_MF2, 32);
    k_mixmodes<<<NI, 256>>>(p_MF2, wM0, p_MF);
    k_invrow<<<NI, 256>>>(p_MF, p_ptmp, 32, 128);
    k_invcol<<<NI, 256>>>(p_ptmp, p_fno, 32, 128);
    k_inorm<<<NI, 256>>>(p_fno, nullptr, p_fno, ng, nb, 3, nullptr);
    k_mixeps<<<NI * HW / 256, 256>>>(p_m, p_fno, p_an, wM0s, bM0s, 1);

    // mixer layer 1 (norm idx4, no act)
    k_fwd1<32><<<dim3(NI, 16), 256>>>(p_m, p_MF1);
    k_fwd2<<<NI, 256>>>(p_MF1, p_MF2, 32);
    k_mixmodes<<<NI, 256>>>(p_MF2, wM1, p_MF);
    k_invrow<<<NI, 256>>>(p_MF, p_ptmp, 32, 128);
    k_invcol<<<NI, 256>>>(p_ptmp, p_fno, 32, 128);
    k_inorm<<<NI, 256>>>(p_fno, nullptr, p_fno, ng, nb, 4, nullptr);
    k_mixeps<<<NI * HW / 256, 256>>>(p_m, p_fno, p_m, wM1s, bM1s, 0);

    // output = IN(m) (idx5) + attention
    k_inorm<<<NI, 256>>>(p_m, nullptr, out, ng, nb, 5, p_att);
}

// round 7
// speedup vs baseline: 3.8058x; 3.8058x over previous
#include <cuda_runtime.h>
#include <cuda_bf16.h>
#include <cstdint>
#include <cstddef>

#define NI 64
#define NH 32
#define HW 16384

__device__ float d_c[128];
__device__ float d_s[128];

__device__ float s_xan [NI*HW];
__device__ float s_F1  [NI*128*33*2];
__device__ float s_F2  [NI*64*33*2];
__device__ float s_rtmp[NI*64*33*2];
__device__ float s_R64 [NI*64*64];
__device__ float s_t64 [(size_t)NI*NH*64*16*2];
__device__ float s_k   [(size_t)NI*NH*64*64];
__device__ float s_q   [(size_t)NI*NH*64*64];
__device__ float s_attn[64*1024];
__device__ float s_vhat [(size_t)NI*NH*4096];
__device__ float s_svhat[(size_t)NI*NH*1024];
__device__ float s_ghat [(size_t)NI*NH*4096];
__device__ float s_sghat[(size_t)NI*NH*1024];
__device__ float s_PF  [NI*64*32*2];
__device__ float s_ptmp[NI*128*32*2];
__device__ float s_y2  [NI*HW];
__device__ float s_fno [NI*HW];
__device__ float s_att [NI*HW];
__device__ float s_an  [NI*HW];
__device__ float s_m   [NI*HW];
__device__ float s_MF1 [NI*128*32*2];
__device__ float s_MF2 [NI*64*32*2];
__device__ float s_MF  [NI*64*32*2];

__device__ __forceinline__ void load_tables(float* cs, float* ss) {
    for (int t = threadIdx.x; t < 128; t += blockDim.x) { cs[t] = d_c[t]; ss[t] = d_s[t]; }
}

__global__ void k_init() {
    int k = threadIdx.x;
    d_c[k] = cospif(k / 64.0f);
    d_s[k] = sinpif(k / 64.0f);
}

// instance norm per image; optional pre-add and post-add
__global__ void k_inorm(const float* __restrict__ src, const float* __restrict__ add,
                        float* __restrict__ dst, const float* __restrict__ gA,
                        const float* __restrict__ bA, int gi, const float* __restrict__ post) {
    int img = blockIdx.x, tid = threadIdx.x;
    const float* s = src + (size_t)img * HW;
    const float* a = add ? add + (size_t)img * HW : nullptr;
    float sum = 0.f, sq = 0.f;
    for (int p = tid; p < HW; p += 256) {
        float v = s[p]; if (a) v += a[p];
        sum += v; sq += v * v;
    }
    __shared__ float r1[256], r2[256];
    r1[tid] = sum; r2[tid] = sq; __syncthreads();
    for (int st = 128; st > 0; st >>= 1) {
        if (tid < st) { r1[tid] += r1[tid + st]; r2[tid] += r2[tid + st]; }
        __syncthreads();
    }
    __shared__ float mean_s, istd_s;
    if (tid == 0) {
        float m = r1[0] * (1.f / HW);
        float var = r2[0] * (1.f / HW) - m * m;
        mean_s = m; istd_s = rsqrtf(var + 1e-5f);
    }
    __syncthreads();
    float g = gA[gi], bb = bA[gi], m = mean_s, is = istd_s;
    for (int p = tid; p < HW; p += 256) {
        float v = s[p]; if (a) v += a[p];
        float r = (v - m) * is * g + bb;
        if (post) r += post[(size_t)img * HW + p];
        dst[(size_t)img * HW + p] = r;
    }
}

// fwd partial DFT stage1 (cols)
template <int NC>
__global__ void k_fwd1(const float* __restrict__ x, float* __restrict__ out) {
    int n = blockIdx.x, hb = blockIdx.y;
    __shared__ float xs[8 * 128];
    __shared__ float cs[128], ss[128];
    load_tables(cs, ss);
    for (int t = threadIdx.x; t < 8 * 128; t += blockDim.x)
        xs[t] = x[((size_t)n * 128 + hb * 8) * 128 + t];
    __syncthreads();
    int t = threadIdx.x;
    if (t >= 8 * NC) return;
    int hl = t / NC, c = t % NC;
    float re = 0.f, im = 0.f;
    int idx = 0;
    #pragma unroll 4
    for (int w = 0; w < 128; w++) {
        float v = xs[hl * 128 + w];
        re += v * cs[idx]; im -= v * ss[idx];
        idx = (idx + c) & 127;
    }
    int h = hb * 8 + hl;
    size_t o = ((size_t)(n * 128 + h) * NC + c) * 2;
    out[o] = re * (1.f / 128.f); out[o + 1] = im * (1.f / 128.f);
}

// fwd stage2 (rows), split over gridDim.y
__global__ void k_fwd2(const float* __restrict__ F1, float* __restrict__ F2o, int NC) {
    int n = blockIdx.x;
    int S = gridDim.y, chunk = 64 / S, jr0 = blockIdx.y * chunk;
    __shared__ float fs[128 * 33 * 2];
    __shared__ float cs[128], ss[128];
    load_tables(cs, ss);
    int tot = 128 * NC * 2;
    for (int t = threadIdx.x; t < tot; t += blockDim.x)
        fs[t] = F1[(size_t)n * tot + t];
    __syncthreads();
    for (int o = threadIdx.x; o < chunk * NC; o += blockDim.x) {
        int jr = jr0 + o / NC, c = o % NC;
        int r = jr < 32 ? jr : jr + 64;
        float re = 0.f, im = 0.f;
        int idx = 0;
        #pragma unroll 4
        for (int h = 0; h < 128; h++) {
            float ar = fs[(h * NC + c) * 2], ai = fs[(h * NC + c) * 2 + 1];
            float tc = cs[idx], ts = ss[idx];
            re += ar * tc + ai * ts;
            im += ai * tc - ar * ts;
            idx = (idx + r) & 127;
        }
        size_t oo = ((size_t)(n * 64 + jr) * NC + c) * 2;
        F2o[oo] = re * (1.f / 128.f); F2o[oo + 1] = im * (1.f / 128.f);
    }
}

// row inverse, split over gridDim.y
__global__ void k_invrow(const float* __restrict__ src, float* __restrict__ dst, int NC, int P) {
    int n = blockIdx.x;
    int S = gridDim.y, chunk = P / S, y0 = blockIdx.y * chunk;
    __shared__ float fs[64 * 33 * 2];
    __shared__ float cs[128], ss[128];
    load_tables(cs, ss);
    int tot = 64 * NC * 2;
    for (int t = threadIdx.x; t < tot; t += blockDim.x)
        fs[t] = src[(size_t)n * tot + t];
    __syncthreads();
    int step = 128 / P;
    for (int o = threadIdx.x; o < chunk * NC; o += blockDim.x) {
        int y = y0 + o / NC, c = o % NC;
        float re = 0.f, im = 0.f;
        for (int jr = 0; jr < 64; jr++) {
            int bin = jr < 32 ? jr : jr + (P - 64);
            int idx = (bin * y * step) & 127;
            float ar = fs[(jr * NC + c) * 2], ai = fs[(jr * NC + c) * 2 + 1];
            float tc = cs[idx], ts = ss[idx];
            re += ar * tc - ai * ts;
            im += ar * ts + ai * tc;
        }
        size_t oo = ((size_t)(n * P + y) * NC + c) * 2;
        dst[oo] = re; dst[oo + 1] = im;
    }
}

// c2r col inverse, split over gridDim.y, optional per-image pixel add
__global__ void k_invcol(const float* __restrict__ tmp, float* __restrict__ dst, int NC, int P,
                         const float* __restrict__ yadd) {
    int n = blockIdx.x;
    int PP = P * P;
    int S = gridDim.y, chunk = PP / S, p0 = blockIdx.y * chunk;
    __shared__ float ts_[128 * 32 * 2];
    __shared__ float cs[128], ss[128];
    load_tables(cs, ss);
    int tot = P * NC * 2;
    for (int t = threadIdx.x; t < tot; t += blockDim.x)
        ts_[t] = tmp[(size_t)n * tot + t];
    __syncthreads();
    int nyq = ((NC - 1) * 2 == P) ? 1 : 0;
    int cmax = nyq ? NC - 1 : NC;
    int step = 128 / P;
    for (int pi = threadIdx.x; pi < chunk; pi += blockDim.x) {
        int p = p0 + pi;
        int y = p / P, x = p % P;
        const float* row = ts_ + y * NC * 2;
        float acc = row[0];
        for (int c = 1; c < cmax; c++) {
            int idx = (c * x * step) & 127;
            acc += 2.f * (row[2 * c] * cs[idx] - row[2 * c + 1] * ss[idx]);
        }
        if (nyq) {
            int idx = ((NC - 1) * x * step) & 127;
            acc += row[(NC - 1) * 2] * cs[idx];
        }
        if (yadd) acc += yadd[(size_t)n * PP + p];
        dst[(size_t)n * PP + p] = acc;
    }
}

// K/Q: mode multiply + row inverse
__global__ void k_invrow_kqv(const float* __restrict__ F2src, const float* __restrict__ w,
                             float* __restrict__ dst, int P) {
    int i = blockIdx.x, o = blockIdx.y;
    __shared__ float fw[32 * 16 * 2];
    __shared__ float cs[128], ss[128];
    load_tables(cs, ss);
    for (int t = threadIdx.x; t < 512; t += blockDim.x) {
        int jj = t >> 4, c = t & 15;
        int jr = jj < 16 ? jj : jj + 32;
        int sgn = jj < 16 ? 0 : 1, jjm = jj & 15;
        float ar = F2src[((size_t)(i * 64 + jr) * 33 + c) * 2];
        float ai = F2src[((size_t)(i * 64 + jr) * 33 + c) * 2 + 1];
        const float* wp = w + (((size_t)(sgn * 32 + o) * 16 + jjm) * 16 + c) * 2;
        float wr = wp[0], wi = wp[1];
        fw[t * 2]     = ar * wr - ai * wi;
        fw[t * 2 + 1] = ar * wi + ai * wr;
    }
    __syncthreads();
    int step = 128 / P;
    for (int t = threadIdx.x; t < P * 16; t += blockDim.x) {
        int y = t >> 4, c = t & 15;
        float re = 0.f, im = 0.f;
        #pragma unroll
        for (int jj = 0; jj < 32; jj++) {
            int bin = jj < 16 ? jj : jj + (P - 32);
            int idx = (bin * y * step) & 127;
            float ar = fw[(jj * 16 + c) * 2], ai = fw[(jj * 16 + c) * 2 + 1];
            re += ar * cs[idx] - ai * ss[idx];
            im += ar * ss[idx] + ai * cs[idx];
        }
        size_t oo = (((size_t)(i * 32 + o) * P + y) * 16 + c) * 2;
        dst[oo] = re; dst[oo + 1] = im;
    }
}

// K/Q c2r + fused per-head skip
__global__ void k_invcol_skip(const float* __restrict__ tmp, const float* __restrict__ skipsrc,
                              const float* __restrict__ ws, const float* __restrict__ bs,
                              float* __restrict__ dst, int P) {
    int img = blockIdx.x;
    int i = img >> 5, o = img & 31;
    __shared__ float ts_[128 * 16 * 2];
    __shared__ float cs[128], ss[128];
    load_tables(cs, ss);
    int tot = P * 32;
    for (int t = threadIdx.x; t < tot; t += blockDim.x)
        ts_[t] = tmp[(size_t)img * tot + t];
    __syncthreads();
    float wsv = ws[o], bsv = bs[o];
    int step = 128 / P;
    int PP = P * P;
    for (int p = threadIdx.x; p < PP; p += blockDim.x) {
        int y = p / P, x = p % P;
        const float* row = ts_ + y * 32;
        float acc = row[0];
        #pragma unroll
        for (int c = 1; c < 16; c++) {
            int idx = (c * x * step) & 127;
            acc += 2.f * (row[2 * c] * cs[idx] - row[2 * c + 1] * ss[idx]);
        }
        dst[(size_t)img * PP + p] = acc + wsv * skipsrc[(size_t)i * PP + p] + bsv;
    }
}

// scores + softmax: 256 threads, 2x2 register tile
__global__ void k_scores(const float* __restrict__ q, const float* __restrict__ k,
                         float* __restrict__ attn) {
    int bh = blockIdx.x, b = bh >> 5, h = bh & 31;
    int tid = threadIdx.x;
    int ti = tid >> 4, si = tid & 15;
    __shared__ float qs_[32 * 132], ks_[32 * 132];
    float a00 = 0.f, a01 = 0.f, a10 = 0.f, a11 = 0.f;
    for (int kk = 0; kk < 4096; kk += 128) {
        __syncthreads();
        for (int t = tid; t < 4096; t += 256) {
            int row = t >> 7, col = t & 127;
            size_t base = (size_t)((b * 32 + row) * 32 + h) * 4096 + kk + col;
            qs_[row * 132 + col] = q[base];
            ks_[row * 132 + col] = k[base];
        }
        __syncthreads();
        #pragma unroll 4
        for (int j = 0; j < 128; j++) {
            float q0 = qs_[(2 * ti) * 132 + j], q1 = qs_[(2 * ti + 1) * 132 + j];
            float k0 = ks_[(2 * si) * 132 + j], k1 = ks_[(2 * si + 1) * 132 + j];
            a00 += q0 * k0; a01 += q0 * k1; a10 += q1 * k0; a11 += q1 * k1;
        }
    }
    float sc = 1.f / 64.f;
    a00 *= sc; a01 *= sc; a10 *= sc; a11 *= sc;
    float m0 = fmaxf(a00, a01), m1v = fmaxf(a10, a11);
    for (int o = 8; o > 0; o >>= 1) {
        m0  = fmaxf(m0,  __shfl_xor_sync(0xffffffffu, m0,  o));
        m1v = fmaxf(m1v, __shfl_xor_sync(0xffffffffu, m1v, o));
    }
    float e00 = expf(a00 - m0), e01 = expf(a01 - m0);
    float e10 = expf(a10 - m1v), e11 = expf(a11 - m1v);
    float s0 = e00 + e01, s1 = e10 + e11;
    for (int o = 8; o > 0; o >>= 1) {
        s0 += __shfl_xor_sync(0xffffffffu, s0, o);
        s1 += __shfl_xor_sync(0xffffffffu, s1, o);
    }
    float* ap = attn + (size_t)bh * 1024;
    ap[(2 * ti) * 32 + 2 * si]         = e00 / s0;
    ap[(2 * ti) * 32 + 2 * si + 1]     = e01 / s0;
    ap[(2 * ti + 1) * 32 + 2 * si]     = e10 / s1;
    ap[(2 * ti + 1) * 32 + 2 * si + 1] = e11 / s1;
}

// Build Vhat (64x32 modes of v image, exact incl. col-0 symmetrization) and raw SpecVhat
__global__ void k_vhat(const float* __restrict__ F2, const float* __restrict__ wV,
                       const float* __restrict__ wVs, const float* __restrict__ bVs,
                       float* __restrict__ vhat, float* __restrict__ svhat) {
    int i = blockIdx.x, h = blockIdx.y;
    __shared__ float f2s[64 * 33 * 2];
    __shared__ float wv_s[1024];   // [sgn 2][jm 16][c 16][2]
    for (int t = threadIdx.x; t < 64 * 33 * 2; t += blockDim.x)
        f2s[t] = F2[(size_t)i * (64 * 33 * 2) + t];
    for (int t = threadIdx.x; t < 1024; t += blockDim.x) {
        int sgn = t >> 9;
        wv_s[t] = wV[((size_t)(sgn * 32 + h) * 256) * 2 + (t & 511)];
    }
    __syncthreads();
    float wvsv = wVs[h], bvsv = bVs[h];

    #define OF(JJ, CC, ORR, OII) { int sg_ = (JJ) < 16 ? 0 : 1; int jm_ = (JJ) < 16 ? (JJ) : (JJ) - 48; \
        float fr_ = f2s[((JJ) * 33 + (CC)) * 2], fi_ = f2s[((JJ) * 33 + (CC)) * 2 + 1]; \
        float wr_ = wv_s[sg_ * 512 + (jm_ * 16 + (CC)) * 2], wi_ = wv_s[sg_ * 512 + (jm_ * 16 + (CC)) * 2 + 1]; \
        ORR = fr_ * wr_ - fi_ * wi_; OII = fr_ * wi_ + fi_ * wr_; }

    for (int t = threadIdx.x; t < 2048; t += blockDim.x) {
        int jj = t >> 5, c = t & 31;
        float fr = f2s[(jj * 33 + c) * 2], fi = f2s[(jj * 33 + c) * 2 + 1];
        float vr = wvsv * fr, vi = wvsv * fi;
        if (jj == 0 && c == 0) vr += bvsv;
        if (c >= 1 && c < 16 && (jj < 16 || jj >= 48)) {
            float orr, oii; OF(jj, c, orr, oii);
            vr += orr; vi += oii;
        } else if (c == 0) {
            if (jj == 0) {
                float orr, oii; OF(0, 0, orr, oii); (void)oii;
                vr += orr;
            } else if (jj <= 15) {
                float o1r, o1i, o2r, o2i;
                OF(jj, 0, o1r, o1i); OF(64 - jj, 0, o2r, o2i);
                vr += 0.5f * (o1r + o2r); vi += 0.5f * (o1i - o2i);
            } else if (jj == 16) {
                float orr, oii; OF(48, 0, orr, oii);
                vr += 0.5f * orr; vi -= 0.5f * oii;
            } else if (jj == 48) {
                float orr, oii; OF(48, 0, orr, oii);
                vr += 0.5f * orr; vi += 0.5f * oii;
            } else if (jj >= 49) {
                float o1r, o1i, o2r, o2i;
                OF(jj, 0, o1r, o1i); OF(64 - jj, 0, o2r, o2i);
                vr += 0.5f * (o1r + o2r); vi += 0.5f * (o1i - o2i);
            }
        }
        size_t oo = ((size_t)(i * 32 + h) * 2048 + t) * 2;
        vhat[oo] = vr; vhat[oo + 1] = vi;
    }
    // raw SpecVhat (placed coefficients, no symmetrization)
    for (int t = threadIdx.x; t < 512; t += blockDim.x) {
        int jm = t >> 4, c = t & 15;
        int jj = jm < 16 ? jm : jm + 32;
        float orr, oii; OF(jj, c, orr, oii);
        size_t oo = ((size_t)(i * 32 + h) * 512 + t) * 2;
        svhat[oo] = orr; svhat[oo + 1] = oii;
    }
    #undef OF
}

// Ghat = attn x Vhat per (b,h); generic over ncols
__global__ void k_ghat(const float* __restrict__ attn, const float* __restrict__ vin,
                       float* __restrict__ gout, int ncols) {
    int b = blockIdx.x, h = blockIdx.y, c0 = blockIdx.z * 256;
    __shared__ float a_sh[1024];
    __shared__ float vs[32 * 256];
    for (int t = threadIdx.x; t < 1024; t += 256)
        a_sh[t] = attn[(size_t)(b * 32 + h) * 1024 + t];
    for (int t = threadIdx.x; t < 8192; t += 256) {
        int s = t >> 8, c = t & 255;
        vs[t] = vin[(size_t)((b * 32 + s) * 32 + h) * ncols + c0 + c];
    }
    __syncthreads();
    int tq = threadIdx.x >> 5;   // 8 groups x 4 t
    int cg = threadIdx.x & 31;   // 32 groups x 8 cols
    float acc[4][8];
    #pragma unroll
    for (int r = 0; r < 4; r++)
        #pragma unroll
        for (int cc = 0; cc < 8; cc++) acc[r][cc] = 0.f;
    for (int s = 0; s < 32; s++) {
        float a0 = a_sh[(tq * 4 + 0) * 32 + s];
        float a1 = a_sh[(tq * 4 + 1) * 32 + s];
        float a2 = a_sh[(tq * 4 + 2) * 32 + s];
        float a3 = a_sh[(tq * 4 + 3) * 32 + s];
        const float* vp = vs + s * 256 + cg * 8;
        #pragma unroll
        for (int cc = 0; cc < 8; cc++) {
            float v = vp[cc];
            acc[0][cc] += a0 * v; acc[1][cc] += a1 * v;
            acc[2][cc] += a2 * v; acc[3][cc] += a3 * v;
        }
    }
    #pragma unroll
    for (int r = 0; r < 4; r++)
        #pragma unroll
        for (int cc = 0; cc < 8; cc++)
            gout[(size_t)((b * 32 + tq * 4 + r) * 32 + h) * ncols + c0 + cg * 8 + cc] = acc[r][cc];
}

// PF = sum_h wP*Ghat  (+ M = sum_h wPs*SpecGhat folded into spec window)
__global__ void k_pf(const float* __restrict__ ghat, const float* __restrict__ sghat,
                     const float* __restrict__ wP, const float* __restrict__ wPs,
                     float* __restrict__ PF) {
    int i = blockIdx.x;
    int t = blockIdx.y * 256 + threadIdx.x;
    __shared__ float wps_[32];
    if (threadIdx.x < 32) wps_[threadIdx.x] = wPs[threadIdx.x];
    __syncthreads();
    int jj = t >> 5, c = t & 31;
    int sgn = jj < 32 ? 0 : 1, jjm = jj & 31;
    float re = 0.f, im = 0.f;
    for (int h = 0; h < 32; h++) {
        const float* g = ghat + ((size_t)(i * 32 + h) * 2048 + t) * 2;
        const float* wp = wP + (((size_t)(sgn * 32 + h) * 32 + jjm) * 32 + c) * 2;
        float ar = g[0], ai = g[1], wr = wp[0], wi = wp[1];
        re += ar * wr - ai * wi;
        im += ar * wi + ai * wr;
    }
    if (c < 16 && (jj < 16 || jj >= 48)) {
        int jmp = jj < 16 ? jj : jj - 32;
        for (int h = 0; h < 32; h++) {
            const float* sg = sghat + ((size_t)(i * 32 + h) * 512 + jmp * 16 + c) * 2;
            re += wps_[h] * sg[0]; im += wps_[h] * sg[1];
        }
    }
    size_t oo = ((size_t)i * 2048 + t) * 2;
    PF[oo] = re; PF[oo + 1] = im;
}

// y2[b,t,p] = sum_s C[b,t,s] * xan[(b,s),p] + (bPs + sum_h wPs*bVs),  C = sum_h wPs*wVs*attn
__global__ void k_tokmix(const float* __restrict__ attn, const float* __restrict__ xan,
                         const float* __restrict__ wPs, const float* __restrict__ wVs,
                         const float* __restrict__ bVs, const float* __restrict__ bPs,
                         float* __restrict__ y2) {
    int b = blockIdx.x;
    int pbase = blockIdx.y * 256;
    int tid = threadIdx.x;
    __shared__ float C[1024];
    __shared__ float xs[32 * 256];
    __shared__ float cb_s;
    {
        int t = tid >> 3, s0 = (tid & 7) * 4;
        float c0 = 0.f, c1 = 0.f, c2 = 0.f, c3 = 0.f;
        for (int h = 0; h < 32; h++) {
            float w = wPs[h] * wVs[h];
            const float* ap = attn + (size_t)(b * 32 + h) * 1024 + t * 32 + s0;
            c0 += w * ap[0]; c1 += w * ap[1]; c2 += w * ap[2]; c3 += w * ap[3];
        }
        C[t * 32 + s0] = c0; C[t * 32 + s0 + 1] = c1;
        C[t * 32 + s0 + 2] = c2; C[t * 32 + s0 + 3] = c3;
    }
    if (tid == 0) {
        float cb = bPs[0];
        for (int h = 0; h < 32; h++) cb += wPs[h] * bVs[h];
        cb_s = cb;
    }
    for (int t = tid; t < 8192; t += 256) {
        int s = t >> 8, c = t & 255;
        xs[t] = xan[(size_t)(b * 32 + s) * HW + pbase + c];
    }
    __syncthreads();
    int t = tid >> 3, pg = tid & 7;
    float acc[32];
    #pragma unroll
    for (int pp = 0; pp < 32; pp++) acc[pp] = 0.f;
    for (int s = 0; s < 32; s++) {
        float cc = C[t * 32 + s];
        const float* xp = xs + s * 256 + pg * 32;
        #pragma unroll
        for (int pp = 0; pp < 32; pp++) acc[pp] += cc * xp[pp];
    }
    float cb = cb_s;
    #pragma unroll
    for (int pp = 0; pp < 32; pp++)
        y2[(size_t)(b * 32 + t) * HW + pbase + pg * 32 + pp] = acc[pp] + cb;
}

__global__ void k_mixmodes(const float* __restrict__ F2m, const float* __restrict__ w,
                           float* __restrict__ MF) {
    int i = blockIdx.x;
    for (int t = threadIdx.x; t < 64 * 32; t += blockDim.x) {
        int jj = t >> 5, c = t & 31;
        int sgn = jj < 32 ? 0 : 1, jjm = jj & 31;
        const float* g = F2m + ((size_t)(i * 64 + jj) * 32 + c) * 2;
        const float* wp = w + (((size_t)sgn * 32 + jjm) * 32 + c) * 2;
        float ar = g[0], ai = g[1], wr = wp[0], wi = wp[1];
        size_t oo = ((size_t)(i * 64 + jj) * 32 + c) * 2;
        MF[oo] = ar * wr - ai * wi;
        MF[oo + 1] = ar * wi + ai * wr;
    }
}

__global__ void k_mixeps(float* __restrict__ dst, const float* __restrict__ fn,
                         const float* __restrict__ src, const float* __restrict__ ws,
                         const float* __restrict__ bs, int dogelu) {
    size_t id = (size_t)blockIdx.x * 256 + threadIdx.x;
    float v = fn[id] + ws[0] * src[id] + bs[0];
    if (dogelu) v = 0.5f * v * (1.f + erff(v * 0.70710678118654752f));
    dst[id] = v;
}

extern "C" void kernel_launch(void* const* d_in, const int* in_sizes, int n_in,
                              void* d_out, int out_size) {
    const float* x    = (const float*)d_in[0];
    const float* wK   = (const float*)d_in[1];
    const float* wKs  = (const float*)d_in[2];
    const float* bKs  = (const float*)d_in[3];
    const float* wQ   = (const float*)d_in[4];
    const float* wQs  = (const float*)d_in[5];
    const float* bQs  = (const float*)d_in[6];
    const float* wV   = (const float*)d_in[7];
    const float* wVs  = (const float*)d_in[8];
    const float* bVs  = (const float*)d_in[9];
    const float* wP   = (const float*)d_in[10];
    const float* wPs  = (const float*)d_in[11];
    const float* bPs  = (const float*)d_in[12];
    const float* wM0  = (const float*)d_in[13];
    const float* wM0s = (const float*)d_in[14];
    const float* bM0s = (const float*)d_in[15];
    const float* wM1  = (const float*)d_in[16];
    const float* wM1s = (const float*)d_in[17];
    const float* bM1s = (const float*)d_in[18];
    const float* ng   = (const float*)d_in[19];
    const float* nb   = (const float*)d_in[20];
    float* out = (float*)d_out;

    float *p_xan, *p_F1, *p_F2, *p_rtmp, *p_R64, *p_t64, *p_k, *p_q, *p_attn;
    float *p_vhat, *p_svhat, *p_ghat, *p_sghat, *p_PF, *p_ptmp, *p_y2;
    float *p_fno, *p_att, *p_an, *p_m, *p_MF1, *p_MF2, *p_MF;
    cudaGetSymbolAddress((void**)&p_xan,   s_xan);
    cudaGetSymbolAddress((void**)&p_F1,    s_F1);
    cudaGetSymbolAddress((void**)&p_F2,    s_F2);
    cudaGetSymbolAddress((void**)&p_rtmp,  s_rtmp);
    cudaGetSymbolAddress((void**)&p_R64,   s_R64);
    cudaGetSymbolAddress((void**)&p_t64,   s_t64);
    cudaGetSymbolAddress((void**)&p_k,     s_k);
    cudaGetSymbolAddress((void**)&p_q,     s_q);
    cudaGetSymbolAddress((void**)&p_attn,  s_attn);
    cudaGetSymbolAddress((void**)&p_vhat,  s_vhat);
    cudaGetSymbolAddress((void**)&p_svhat, s_svhat);
    cudaGetSymbolAddress((void**)&p_ghat,  s_ghat);
    cudaGetSymbolAddress((void**)&p_sghat, s_sghat);
    cudaGetSymbolAddress((void**)&p_PF,    s_PF);
    cudaGetSymbolAddress((void**)&p_ptmp,  s_ptmp);
    cudaGetSymbolAddress((void**)&p_y2,    s_y2);
    cudaGetSymbolAddress((void**)&p_fno,   s_fno);
    cudaGetSymbolAddress((void**)&p_att,   s_att);
    cudaGetSymbolAddress((void**)&p_an,    s_an);
    cudaGetSymbolAddress((void**)&p_m,     s_m);
    cudaGetSymbolAddress((void**)&p_MF1,   s_MF1);
    cudaGetSymbolAddress((void**)&p_MF2,   s_MF2);
    cudaGetSymbolAddress((void**)&p_MF,    s_MF);

    k_init<<<1, 128>>>();

    // xa_n (norm idx0) and its partial spectrum
    k_inorm<<<NI, 256>>>(x, nullptr, p_xan, ng, nb, 0, nullptr);
    k_fwd1<33><<<dim3(NI, 16), 264>>>(p_xan, p_F1);
    k_fwd2<<<dim3(NI, 4), 256>>>(p_F1, p_F2, 33);

    // shared K/Q skip (resampled xa_n, 64x64)
    k_invrow<<<dim3(NI, 2), 256>>>(p_F2, p_rtmp, 33, 64);
    k_invcol<<<dim3(NI, 2), 256>>>(p_rtmp, p_R64, 33, 64, nullptr);

    // K, Q at half res
    k_invrow_kqv<<<dim3(NI, NH), 256>>>(p_F2, wK, p_t64, 64);
    k_invcol_skip<<<NI * NH, 256>>>(p_t64, p_R64, wKs, bKs, p_k, 64);
    k_invrow_kqv<<<dim3(NI, NH), 256>>>(p_F2, wQ, p_t64, 64);
    k_invcol_skip<<<NI * NH, 256>>>(p_t64, p_R64, wQs, bQs, p_q, 64);

    // attention weights
    k_scores<<<64, 256>>>(p_q, p_k, p_attn);

    // mode-space V, attention, projection
    k_vhat<<<dim3(NI, NH), 256>>>(p_F2, wV, wVs, bVs, p_vhat, p_svhat);
    k_ghat<<<dim3(2, 32, 16), 256>>>(p_attn, p_vhat, p_ghat, 4096);
    k_ghat<<<dim3(2, 32, 4), 256>>>(p_attn, p_svhat, p_sghat, 1024);
    k_pf<<<dim3(NI, 8), 256>>>(p_ghat, p_sghat, wP, wPs, p_PF);
    k_tokmix<<<dim3(2, 64), 256>>>(p_attn, p_xan, wPs, wVs, bVs, bPs, p_y2);
    k_invrow<<<dim3(NI, 4), 256>>>(p_PF, p_ptmp, 32, 128);
    k_invcol<<<dim3(NI, 8), 256>>>(p_ptmp, p_fno, 32, 128, p_y2);

    // attention = IN(projd + xa) (idx1); an = IN(attention) (idx2)
    k_inorm<<<NI, 256>>>(p_fno, x, p_att, ng, nb, 1, nullptr);
    k_inorm<<<NI, 256>>>(p_att, nullptr, p_an, ng, nb, 2, nullptr);

    // mixer layer 0 (norm idx3 + gelu)
    k_fwd1<32><<<dim3(NI, 16), 256>>>(p_an, p_MF1);
    k_fwd2<<<dim3(NI, 4), 256>>>(p_MF1, p_MF2, 32);
    k_mixmodes<<<NI, 256>>>(p_MF2, wM0, p_MF);
    k_invrow<<<dim3(NI, 4), 256>>>(p_MF, p_ptmp, 32, 128);
    k_invcol<<<dim3(NI, 8), 256>>>(p_ptmp, p_fno, 32, 128, nullptr);
    k_inorm<<<NI, 256>>>(p_fno, nullptr, p_fno, ng, nb, 3, nullptr);
    k_mixeps<<<NI * HW / 256, 256>>>(p_m, p_fno, p_an, wM0s, bM0s, 1);

    // mixer layer 1 (norm idx4)
    k_fwd1<32><<<dim3(NI, 16), 256>>>(p_m, p_MF1);
    k_fwd2<<<dim3(NI, 4), 256>>>(p_MF1, p_MF2, 32);
    k_mixmodes<<<NI, 256>>>(p_MF2, wM1, p_MF);
    k_invrow<<<dim3(NI, 4), 256>>>(p_MF, p_ptmp, 32, 128);
    k_invcol<<<dim3(NI, 8), 256>>>(p_ptmp, p_fno, 32, 128, nullptr);
    k_inorm<<<NI, 256>>>(p_fno, nullptr, p_fno, ng, nb, 4, nullptr);
    k_mixeps<<<NI * HW / 256, 256>>>(p_m, p_fno, p_m, wM1s, bM1s, 0);

    // output = IN(m) (idx5) + attention
    k_inorm<<<NI, 256>>>(p_m, nullptr, out, ng, nb, 5, p_att);
}

// round 8
// speedup vs baseline: 5.2606x; 1.3822x over previous
#include <cuda_runtime.h>
#include <cuda_bf16.h>
#include <cstdint>
#include <cstddef>

#define NI 64
#define NH 32
#define HW 16384

__device__ float d_c[128];
__device__ float d_s[128];

__device__ float s_xan [NI*HW];
__device__ float s_F1  [NI*128*33*2];
__device__ float s_F2  [NI*64*33*2];
__device__ float s_R64 [NI*64*64];
__device__ float s_k   [(size_t)NI*NH*64*64];
__device__ float s_q   [(size_t)NI*NH*64*64];
__device__ float s_attn[64*1024];
__device__ float s_vhat [(size_t)NI*NH*4096];
__device__ float s_svhat[(size_t)NI*NH*1024];
__device__ float s_ghat [(size_t)NI*NH*4096];
__device__ float s_sghat[(size_t)NI*NH*1024];
__device__ float s_PF  [NI*64*32*2];
__device__ float s_y2  [NI*HW];
__device__ float s_fno [NI*HW];
__device__ float s_att [NI*HW];
__device__ float s_an  [NI*HW];
__device__ float s_m   [NI*HW];
__device__ float s_MF1 [NI*128*32*2];
__device__ float s_MF2 [NI*64*32*2];

__device__ __forceinline__ void load_tables(float* cs, float* ss) {
    for (int t = threadIdx.x; t < 128; t += blockDim.x) { cs[t] = d_c[t]; ss[t] = d_s[t]; }
}

__global__ void k_init() {
    int k = threadIdx.x;
    d_c[k] = cospif(k / 64.0f);
    d_s[k] = sinpif(k / 64.0f);
}

// -------- instance norm (512 thr); optional pre-add & post-add
__global__ void k_inorm(const float* __restrict__ src, const float* __restrict__ add,
                        float* __restrict__ dst, const float* __restrict__ gA,
                        const float* __restrict__ bA, int gi, const float* __restrict__ post) {
    int img = blockIdx.x, tid = threadIdx.x;
    const float* s = src + (size_t)img * HW;
    const float* a = add ? add + (size_t)img * HW : nullptr;
    float sum = 0.f, sq = 0.f;
    for (int p = tid; p < HW; p += 512) {
        float v = s[p]; if (a) v += a[p];
        sum += v; sq += v * v;
    }
    __shared__ float r1[512], r2[512];
    r1[tid] = sum; r2[tid] = sq; __syncthreads();
    for (int st = 256; st > 0; st >>= 1) {
        if (tid < st) { r1[tid] += r1[tid + st]; r2[tid] += r2[tid + st]; }
        __syncthreads();
    }
    __shared__ float mean_s, istd_s;
    if (tid == 0) {
        float m = r1[0] * (1.f / HW);
        float var = r2[0] * (1.f / HW) - m * m;
        mean_s = m; istd_s = rsqrtf(var + 1e-5f);
    }
    __syncthreads();
    float g = gA[gi], bb = bA[gi], m = mean_s, is = istd_s;
    for (int p = tid; p < HW; p += 512) {
        float v = s[p]; if (a) v += a[p];
        float r = (v - m) * is * g + bb;
        if (post) r += post[(size_t)img * HW + p];
        dst[(size_t)img * HW + p] = r;
    }
}

// -------- fused IN1(fno+x) -> att, IN2(att) -> an (second norm analytic)
__global__ void k_norm12(const float* __restrict__ fno, const float* __restrict__ x,
                         float* __restrict__ att, float* __restrict__ an,
                         const float* __restrict__ gA, const float* __restrict__ bA) {
    int img = blockIdx.x, tid = threadIdx.x;
    const float* f = fno + (size_t)img * HW;
    const float* xx = x + (size_t)img * HW;
    float sum = 0.f, sq = 0.f;
    for (int p = tid; p < HW; p += 512) {
        float v = f[p] + xx[p];
        sum += v; sq += v * v;
    }
    __shared__ float r1[512], r2[512];
    r1[tid] = sum; r2[tid] = sq; __syncthreads();
    for (int st = 256; st > 0; st >>= 1) {
        if (tid < st) { r1[tid] += r1[tid + st]; r2[tid] += r2[tid + st]; }
        __syncthreads();
    }
    __shared__ float mean_s, istd_s, istd2_s;
    if (tid == 0) {
        float m = r1[0] * (1.f / HW);
        float var = r2[0] * (1.f / HW) - m * m;
        float is1 = rsqrtf(var + 1e-5f);
        float g1 = gA[1];
        float varatt = g1 * g1 * var * is1 * is1;
        mean_s = m; istd_s = is1;
        istd2_s = rsqrtf(varatt + 1e-5f);
    }
    __syncthreads();
    float g1 = gA[1], b1 = bA[1], g2 = gA[2], b2 = bA[2];
    float m = mean_s, is1 = istd_s, is2 = istd2_s;
    for (int p = tid; p < HW; p += 512) {
        float v = f[p] + xx[p];
        float a = (v - m) * is1 * g1 + b1;
        att[(size_t)img * HW + p] = a;
        an[(size_t)img * HW + p] = (a - b1) * is2 * g2 + b2;
    }
}

// -------- fused IN(gi)(src) then dst = [gelu](norm + ws*src2 + bs)
__global__ void k_normeps(const float* __restrict__ src, const float* __restrict__ src2,
                          float* __restrict__ dst, const float* __restrict__ gA,
                          const float* __restrict__ bA, int gi,
                          const float* __restrict__ ws, const float* __restrict__ bs,
                          int dogelu) {
    int img = blockIdx.x, tid = threadIdx.x;
    const float* s = src + (size_t)img * HW;
    float sum = 0.f, sq = 0.f;
    for (int p = tid; p < HW; p += 512) {
        float v = s[p]; sum += v; sq += v * v;
    }
    __shared__ float r1[512], r2[512];
    r1[tid] = sum; r2[tid] = sq; __syncthreads();
    for (int st = 256; st > 0; st >>= 1) {
        if (tid < st) { r1[tid] += r1[tid + st]; r2[tid] += r2[tid + st]; }
        __syncthreads();
    }
    __shared__ float mean_s, istd_s;
    if (tid == 0) {
        float m = r1[0] * (1.f / HW);
        float var = r2[0] * (1.f / HW) - m * m;
        mean_s = m; istd_s = rsqrtf(var + 1e-5f);
    }
    __syncthreads();
    float g = gA[gi], bb = bA[gi], m = mean_s, is = istd_s;
    float wsv = ws[0], bsv = bs[0];
    for (int p = tid; p < HW; p += 512) {
        float v = (s[p] - m) * is * g + bb + wsv * src2[(size_t)img * HW + p] + bsv;
        if (dogelu) v = 0.5f * v * (1.f + erff(v * 0.70710678118654752f));
        dst[(size_t)img * HW + p] = v;
    }
}

// -------- fwd partial DFT stage1 (cols); 4-row batching per thread
template <int NC>
__global__ void k_fwd1(const float* __restrict__ x, float* __restrict__ out) {
    int n = blockIdx.x, hb = blockIdx.y;       // 4 y-blocks of 32 rows
    __shared__ float xs[32 * 128];
    __shared__ float cs[128], ss[128];
    load_tables(cs, ss);
    for (int t = threadIdx.x; t < 32 * 128; t += blockDim.x)
        xs[t] = x[((size_t)n * 128 + hb * 32) * 128 + t];
    __syncthreads();
    int t = threadIdx.x;
    if (t >= 8 * NC) return;
    int hg = t / NC, c = t % NC;
    float rr[4] = {0, 0, 0, 0}, ii[4] = {0, 0, 0, 0};
    int idx = 0;
    #pragma unroll 2
    for (int w = 0; w < 128; w++) {
        float tc = cs[idx], tsn = ss[idx];
        #pragma unroll
        for (int kk = 0; kk < 4; kk++) {
            float v = xs[(hg * 4 + kk) * 128 + w];
            rr[kk] += v * tc; ii[kk] -= v * tsn;
        }
        idx = (idx + c) & 127;
    }
    #pragma unroll
    for (int kk = 0; kk < 4; kk++) {
        int row = hb * 32 + hg * 4 + kk;
        size_t o = ((size_t)(n * 128 + row) * NC + c) * 2;
        out[o] = rr[kk] * (1.f / 128.f); out[o + 1] = ii[kk] * (1.f / 128.f);
    }
}

// -------- fwd stage2 (rows); 4-col batching per thread; split jr over gridDim.y
__global__ void k_fwd2(const float* __restrict__ F1, float* __restrict__ F2o, int NC) {
    int n = blockIdx.x;
    int S = gridDim.y, jrchunk = 64 / S, jr0 = blockIdx.y * jrchunk;
    __shared__ float fs[128 * 33 * 2];
    __shared__ float cs[128], ss[128];
    load_tables(cs, ss);
    int tot = 128 * NC * 2;
    for (int t = threadIdx.x; t < tot; t += blockDim.x)
        fs[t] = F1[(size_t)n * tot + t];
    __syncthreads();
    int CG = (NC + 3) >> 2;
    for (int t = threadIdx.x; t < jrchunk * CG; t += blockDim.x) {
        int jl = t / CG, cg = t % CG;
        int jr = jr0 + jl, c0 = cg * 4;
        int r = jr < 32 ? jr : jr + 64;
        float rr_[4] = {0, 0, 0, 0}, ii_[4] = {0, 0, 0, 0};
        int idx = 0;
        #pragma unroll 2
        for (int h = 0; h < 128; h++) {
            float tc = cs[idx], tsn = ss[idx];
            #pragma unroll
            for (int cc = 0; cc < 4; cc++) {
                if (c0 + cc < NC) {
                    float ar = fs[(h * NC + c0 + cc) * 2], ai = fs[(h * NC + c0 + cc) * 2 + 1];
                    rr_[cc] += ar * tc + ai * tsn;
                    ii_[cc] += ai * tc - ar * tsn;
                }
            }
            idx = (idx + r) & 127;
        }
        #pragma unroll
        for (int cc = 0; cc < 4; cc++) {
            if (c0 + cc < NC) {
                size_t oo = ((size_t)(n * 64 + jr) * NC + c0 + cc) * 2;
                F2o[oo] = rr_[cc] * (1.f / 128.f); F2o[oo + 1] = ii_[cc] * (1.f / 128.f);
            }
        }
    }
}

// -------- fused inverse (row+col) with optional spectral weight multiply and pixel add.
// grid (NI, P/32): each block computes 32 output rows. NC<=33.
__global__ void k_inv2(const float* __restrict__ src, const float* __restrict__ wmul,
                       float* __restrict__ dst, int NC, int P, const float* __restrict__ yadd) {
    int n = blockIdx.x;
    int ybase = blockIdx.y * 32;
    __shared__ float fs[64 * 33 * 2];
    __shared__ float rr[32 * 33 * 2];
    __shared__ float cs[128], ss[128];
    load_tables(cs, ss);
    // stage 1: load modes (+ optional weight multiply)
    for (int t = threadIdx.x; t < 64 * NC; t += blockDim.x) {
        int jj = t / NC, c = t % NC;
        float ar = src[((size_t)n * 64 * NC + t) * 2];
        float ai = src[((size_t)n * 64 * NC + t) * 2 + 1];
        if (wmul) {
            int sgn = jj < 32 ? 0 : 1, jjm = jj & 31;
            const float* wp = wmul + (((size_t)sgn * 32 + jjm) * 32 + c) * 2;
            float wr = wp[0], wi = wp[1];
            float r2 = ar * wr - ai * wi, i2 = ar * wi + ai * wr;
            ar = r2; ai = i2;
        }
        fs[t * 2] = ar; fs[t * 2 + 1] = ai;
    }
    __syncthreads();
    int step = 128 / P;
    // stage 2: row inverse for local 32 rows; 4-c batching
    int CG = (NC + 3) >> 2;
    for (int t = threadIdx.x; t < 32 * CG; t += blockDim.x) {
        int yl = t / CG, cg = t % CG;
        int y = ybase + yl, c0 = cg * 4;
        float accr[4] = {0, 0, 0, 0}, acci[4] = {0, 0, 0, 0};
        for (int jr = 0; jr < 64; jr++) {
            int bin = jr < 32 ? jr : jr + (P - 64);
            int idx = (bin * y * step) & 127;
            float tc = cs[idx], tsn = ss[idx];
            #pragma unroll
            for (int cc = 0; cc < 4; cc++) {
                if (c0 + cc < NC) {
                    float ar = fs[(jr * NC + c0 + cc) * 2], ai = fs[(jr * NC + c0 + cc) * 2 + 1];
                    accr[cc] += ar * tc - ai * tsn;
                    acci[cc] += ar * tsn + ai * tc;
                }
            }
        }
        #pragma unroll
        for (int cc = 0; cc < 4; cc++) {
            if (c0 + cc < NC) {
                rr[(yl * NC + c0 + cc) * 2] = accr[cc];
                rr[(yl * NC + c0 + cc) * 2 + 1] = acci[cc];
            }
        }
    }
    __syncthreads();
    // stage 3: c2r col inverse; 4-y batching with lane-broadcast rr reads
    int nyq = ((NC - 1) * 2 == P) ? 1 : 0;
    int cmax = nyq ? NC - 1 : NC;
    int PP = P * P;
    int slots = 8 * P;   // 8 y-groups of 4 x P columns
    for (int t = threadIdx.x; t < slots; t += blockDim.x) {
        int x = t % P, yg = t / P;
        int yl0 = yg * 4;
        float acc[4];
        #pragma unroll
        for (int yy = 0; yy < 4; yy++) acc[yy] = rr[((yl0 + yy) * NC) * 2];
        for (int c = 1; c < cmax; c++) {
            int idx = (c * x * step) & 127;
            float tc = cs[idx], tsn = ss[idx];
            #pragma unroll
            for (int yy = 0; yy < 4; yy++) {
                float re = rr[((yl0 + yy) * NC + c) * 2], im = rr[((yl0 + yy) * NC + c) * 2 + 1];
                acc[yy] += 2.f * (re * tc - im * tsn);
            }
        }
        if (nyq) {
            int idx = ((NC - 1) * x * step) & 127;
            float tc = cs[idx];
            #pragma unroll
            for (int yy = 0; yy < 4; yy++)
                acc[yy] += rr[((yl0 + yy) * NC + NC - 1) * 2] * tc;
        }
        #pragma unroll
        for (int yy = 0; yy < 4; yy++) {
            int p = (ybase + yl0 + yy) * P + x;
            float v = acc[yy];
            if (yadd) v += yadd[(size_t)n * PP + p];
            dst[(size_t)n * PP + p] = v;
        }
    }
}

// -------- K/Q fully fused: mode-mult + row-inv + col-inv + per-head skip (P=64)
__global__ void k_kq(const float* __restrict__ F2src, const float* __restrict__ w,
                     const float* __restrict__ R64, const float* __restrict__ ws,
                     const float* __restrict__ bs, float* __restrict__ dst) {
    int i = blockIdx.x, o = blockIdx.y;
    __shared__ float fw[32 * 16 * 2];
    __shared__ float rr[64 * 16 * 2];
    __shared__ float cs[128], ss[128];
    load_tables(cs, ss);
    for (int t = threadIdx.x; t < 512; t += blockDim.x) {
        int jj = t >> 4, c = t & 15;
        int jr = jj < 16 ? jj : jj + 32;
        int sgn = jj < 16 ? 0 : 1, jjm = jj & 15;
        float ar = F2src[((size_t)(i * 64 + jr) * 33 + c) * 2];
        float ai = F2src[((size_t)(i * 64 + jr) * 33 + c) * 2 + 1];
        const float* wp = w + (((size_t)(sgn * 32 + o) * 16 + jjm) * 16 + c) * 2;
        float wr = wp[0], wi = wp[1];
        fw[t * 2]     = ar * wr - ai * wi;
        fw[t * 2 + 1] = ar * wi + ai * wr;
    }
    __syncthreads();
    // row inverse: 64 y x 16 c, P=64 -> step 2, bins jj<16->jj else jj+32
    for (int t = threadIdx.x; t < 1024; t += blockDim.x) {
        int y = t >> 4, c = t & 15;
        float re = 0.f, im = 0.f;
        #pragma unroll
        for (int jj = 0; jj < 32; jj++) {
            int bin = jj < 16 ? jj : jj + 32;
            int idx = (bin * y * 2) & 127;
            float ar = fw[(jj * 16 + c) * 2], ai = fw[(jj * 16 + c) * 2 + 1];
            re += ar * cs[idx] - ai * ss[idx];
            im += ar * ss[idx] + ai * cs[idx];
        }
        rr[t * 2] = re; rr[t * 2 + 1] = im;
    }
    __syncthreads();
    float wsv = ws[o], bsv = bs[o];
    size_t obase = (size_t)(i * 32 + o) * 4096;
    for (int t = threadIdx.x; t < 1024; t += blockDim.x) {
        int x = t & 63, yg = t >> 6;
        int y0 = yg * 4;
        float acc[4];
        #pragma unroll
        for (int yy = 0; yy < 4; yy++) acc[yy] = rr[((y0 + yy) * 16) * 2];
        #pragma unroll
        for (int c = 1; c < 16; c++) {
            int idx = (c * x * 2) & 127;
            float tc = cs[idx], tsn = ss[idx];
            #pragma unroll
            for (int yy = 0; yy < 4; yy++) {
                float re = rr[((y0 + yy) * 16 + c) * 2], im = rr[((y0 + yy) * 16 + c) * 2 + 1];
                acc[yy] += 2.f * (re * tc - im * tsn);
            }
        }
        #pragma unroll
        for (int yy = 0; yy < 4; yy++) {
            int p = (y0 + yy) * 64 + x;
            dst[obase + p] = acc[yy] + wsv * R64[(size_t)i * 4096 + p] + bsv;
        }
    }
}

// -------- scores + softmax
__global__ void k_scores(const float* __restrict__ q, const float* __restrict__ k,
                         float* __restrict__ attn) {
    int bh = blockIdx.x, b = bh >> 5, h = bh & 31;
    int tid = threadIdx.x;
    int ti = tid >> 4, si = tid & 15;
    __shared__ float qs_[32 * 132], ks_[32 * 132];
    float a00 = 0.f, a01 = 0.f, a10 = 0.f, a11 = 0.f;
    for (int kk = 0; kk < 4096; kk += 128) {
        __syncthreads();
        for (int t = tid; t < 4096; t += 256) {
            int row = t >> 7, col = t & 127;
            size_t base = (size_t)((b * 32 + row) * 32 + h) * 4096 + kk + col;
            qs_[row * 132 + col] = q[base];
            ks_[row * 132 + col] = k[base];
        }
        __syncthreads();
        #pragma unroll 4
        for (int j = 0; j < 128; j++) {
            float q0 = qs_[(2 * ti) * 132 + j], q1 = qs_[(2 * ti + 1) * 132 + j];
            float k0 = ks_[(2 * si) * 132 + j], k1 = ks_[(2 * si + 1) * 132 + j];
            a00 += q0 * k0; a01 += q0 * k1; a10 += q1 * k0; a11 += q1 * k1;
        }
    }
    float sc = 1.f / 64.f;
    a00 *= sc; a01 *= sc; a10 *= sc; a11 *= sc;
    float m0 = fmaxf(a00, a01), m1v = fmaxf(a10, a11);
    for (int o = 8; o > 0; o >>= 1) {
        m0  = fmaxf(m0,  __shfl_xor_sync(0xffffffffu, m0,  o));
        m1v = fmaxf(m1v, __shfl_xor_sync(0xffffffffu, m1v, o));
    }
    float e00 = expf(a00 - m0), e01 = expf(a01 - m0);
    float e10 = expf(a10 - m1v), e11 = expf(a11 - m1v);
    float s0 = e00 + e01, s1 = e10 + e11;
    for (int o = 8; o > 0; o >>= 1) {
        s0 += __shfl_xor_sync(0xffffffffu, s0, o);
        s1 += __shfl_xor_sync(0xffffffffu, s1, o);
    }
    float* ap = attn + (size_t)bh * 1024;
    ap[(2 * ti) * 32 + 2 * si]         = e00 / s0;
    ap[(2 * ti) * 32 + 2 * si + 1]     = e01 / s0;
    ap[(2 * ti + 1) * 32 + 2 * si]     = e10 / s1;
    ap[(2 * ti + 1) * 32 + 2 * si + 1] = e11 / s1;
}

// -------- Vhat + SpecVhat (exact col-0 symmetrization)
__global__ void k_vhat(const float* __restrict__ F2, const float* __restrict__ wV,
                       const float* __restrict__ wVs, const float* __restrict__ bVs,
                       float* __restrict__ vhat, float* __restrict__ svhat) {
    int i = blockIdx.x, h = blockIdx.y;
    __shared__ float f2s[64 * 33 * 2];
    __shared__ float wv_s[1024];
    for (int t = threadIdx.x; t < 64 * 33 * 2; t += blockDim.x)
        f2s[t] = F2[(size_t)i * (64 * 33 * 2) + t];
    for (int t = threadIdx.x; t < 1024; t += blockDim.x) {
        int sgn = t >> 9;
        wv_s[t] = wV[((size_t)(sgn * 32 + h) * 256) * 2 + (t & 511)];
    }
    __syncthreads();
    float wvsv = wVs[h], bvsv = bVs[h];

    #define OF(JJ, CC, ORR, OII) { int sg_ = (JJ) < 16 ? 0 : 1; int jm_ = (JJ) < 16 ? (JJ) : (JJ) - 48; \
        float fr_ = f2s[((JJ) * 33 + (CC)) * 2], fi_ = f2s[((JJ) * 33 + (CC)) * 2 + 1]; \
        float wr_ = wv_s[sg_ * 512 + (jm_ * 16 + (CC)) * 2], wi_ = wv_s[sg_ * 512 + (jm_ * 16 + (CC)) * 2 + 1]; \
        ORR = fr_ * wr_ - fi_ * wi_; OII = fr_ * wi_ + fi_ * wr_; }

    for (int t = threadIdx.x; t < 2048; t += blockDim.x) {
        int jj = t >> 5, c = t & 31;
        float fr = f2s[(jj * 33 + c) * 2], fi = f2s[(jj * 33 + c) * 2 + 1];
        float vr = wvsv * fr, vi = wvsv * fi;
        if (jj == 0 && c == 0) vr += bvsv;
        if (c >= 1 && c < 16 && (jj < 16 || jj >= 48)) {
            float orr, oii; OF(jj, c, orr, oii);
            vr += orr; vi += oii;
        } else if (c == 0) {
            if (jj == 0) {
                float orr, oii; OF(0, 0, orr, oii); (void)oii;
                vr += orr;
            } else if (jj <= 15) {
                float o1r, o1i, o2r, o2i;
                OF(jj, 0, o1r, o1i); OF(64 - jj, 0, o2r, o2i);
                vr += 0.5f * (o1r + o2r); vi += 0.5f * (o1i - o2i);
            } else if (jj == 16) {
                float orr, oii; OF(48, 0, orr, oii);
                vr += 0.5f * orr; vi -= 0.5f * oii;
            } else if (jj == 48) {
                float orr, oii; OF(48, 0, orr, oii);
                vr += 0.5f * orr; vi += 0.5f * oii;
            } else if (jj >= 49) {
                float o1r, o1i, o2r, o2i;
                OF(jj, 0, o1r, o1i); OF(64 - jj, 0, o2r, o2i);
                vr += 0.5f * (o1r + o2r); vi += 0.5f * (o1i - o2i);
            }
        }
        size_t oo = ((size_t)(i * 32 + h) * 2048 + t) * 2;
        vhat[oo] = vr; vhat[oo + 1] = vi;
    }
    for (int t = threadIdx.x; t < 512; t += blockDim.x) {
        int jm = t >> 4, c = t & 15;
        int jj = jm < 16 ? jm : jm + 32;
        float orr, oii; OF(jj, c, orr, oii);
        size_t oo = ((size_t)(i * 32 + h) * 512 + t) * 2;
        svhat[oo] = orr; svhat[oo + 1] = oii;
    }
    #undef OF
}

// -------- Ghat = attn x Vhat
__global__ void k_ghat(const float* __restrict__ attn, const float* __restrict__ vin,
                       float* __restrict__ gout, int ncols) {
    int b = blockIdx.x, h = blockIdx.y, c0 = blockIdx.z * 256;
    __shared__ float a_sh[1024];
    __shared__ float vs[32 * 256];
    for (int t = threadIdx.x; t < 1024; t += 256)
        a_sh[t] = attn[(size_t)(b * 32 + h) * 1024 + t];
    for (int t = threadIdx.x; t < 8192; t += 256) {
        int s = t >> 8, c = t & 255;
        vs[t] = vin[(size_t)((b * 32 + s) * 32 + h) * ncols + c0 + c];
    }
    __syncthreads();
    int tq = threadIdx.x >> 5;
    int cg = threadIdx.x & 31;
    float acc[4][8];
    #pragma unroll
    for (int r = 0; r < 4; r++)
        #pragma unroll
        for (int cc = 0; cc < 8; cc++) acc[r][cc] = 0.f;
    for (int s = 0; s < 32; s++) {
        float a0 = a_sh[(tq * 4 + 0) * 32 + s];
        float a1 = a_sh[(tq * 4 + 1) * 32 + s];
        float a2 = a_sh[(tq * 4 + 2) * 32 + s];
        float a3 = a_sh[(tq * 4 + 3) * 32 + s];
        const float* vp = vs + s * 256 + cg * 8;
        #pragma unroll
        for (int cc = 0; cc < 8; cc++) {
            float v = vp[cc];
            acc[0][cc] += a0 * v; acc[1][cc] += a1 * v;
            acc[2][cc] += a2 * v; acc[3][cc] += a3 * v;
        }
    }
    #pragma unroll
    for (int r = 0; r < 4; r++)
        #pragma unroll
        for (int cc = 0; cc < 8; cc++)
            gout[(size_t)((b * 32 + tq * 4 + r) * 32 + h) * ncols + c0 + cg * 8 + cc] = acc[r][cc];
}

// -------- PF = sum_h wP*Ghat (+ spec window extras)
__global__ void k_pf(const float* __restrict__ ghat, const float* __restrict__ sghat,
                     const float* __restrict__ wP, const float* __restrict__ wPs,
                     float* __restrict__ PF) {
    int i = blockIdx.x;
    int t = blockIdx.y * 256 + threadIdx.x;
    __shared__ float wps_[32];
    if (threadIdx.x < 32) wps_[threadIdx.x] = wPs[threadIdx.x];
    __syncthreads();
    int jj = t >> 5, c = t & 31;
    int sgn = jj < 32 ? 0 : 1, jjm = jj & 31;
    float re = 0.f, im = 0.f;
    for (int h = 0; h < 32; h++) {
        const float* g = ghat + ((size_t)(i * 32 + h) * 2048 + t) * 2;
        const float* wp = wP + (((size_t)(sgn * 32 + h) * 32 + jjm) * 32 + c) * 2;
        float ar = g[0], ai = g[1], wr = wp[0], wi = wp[1];
        re += ar * wr - ai * wi;
        im += ar * wi + ai * wr;
    }
    if (c < 16 && (jj < 16 || jj >= 48)) {
        int jmp = jj < 16 ? jj : jj - 32;
        for (int h = 0; h < 32; h++) {
            const float* sg = sghat + ((size_t)(i * 32 + h) * 512 + jmp * 16 + c) * 2;
            re += wps_[h] * sg[0]; im += wps_[h] * sg[1];
        }
    }
    size_t oo = ((size_t)i * 2048 + t) * 2;
    PF[oo] = re; PF[oo + 1] = im;
}

// -------- token mix y2
__global__ void k_tokmix(const float* __restrict__ attn, const float* __restrict__ xan,
                         const float* __restrict__ wPs, const float* __restrict__ wVs,
                         const float* __restrict__ bVs, const float* __restrict__ bPs,
                         float* __restrict__ y2) {
    int b = blockIdx.x;
    int pbase = blockIdx.y * 256;
    int tid = threadIdx.x;
    __shared__ float C[1024];
    __shared__ float xs[32 * 256];
    __shared__ float cb_s;
    {
        int t = tid >> 3, s0 = (tid & 7) * 4;
        float c0 = 0.f, c1 = 0.f, c2 = 0.f, c3 = 0.f;
        for (int h = 0; h < 32; h++) {
            float w = wPs[h] * wVs[h];
            const float* ap = attn + (size_t)(b * 32 + h) * 1024 + t * 32 + s0;
            c0 += w * ap[0]; c1 += w * ap[1]; c2 += w * ap[2]; c3 += w * ap[3];
        }
        C[t * 32 + s0] = c0; C[t * 32 + s0 + 1] = c1;
        C[t * 32 + s0 + 2] = c2; C[t * 32 + s0 + 3] = c3;
    }
    if (tid == 0) {
        float cb = bPs[0];
        for (int h = 0; h < 32; h++) cb += wPs[h] * bVs[h];
        cb_s = cb;
    }
    for (int t = tid; t < 8192; t += 256) {
        int s = t >> 8, c = t & 255;
        xs[t] = xan[(size_t)(b * 32 + s) * HW + pbase + c];
    }
    __syncthreads();
    int t = tid >> 3, pg = tid & 7;
    float acc[32];
    #pragma unroll
    for (int pp = 0; pp < 32; pp++) acc[pp] = 0.f;
    for (int s = 0; s < 32; s++) {
        float cc = C[t * 32 + s];
        const float* xp = xs + s * 256 + pg * 32;
        #pragma unroll
        for (int pp = 0; pp < 32; pp++) acc[pp] += cc * xp[pp];
    }
    float cb = cb_s;
    #pragma unroll
    for (int pp = 0; pp < 32; pp++)
        y2[(size_t)(b * 32 + t) * HW + pbase + pg * 32 + pp] = acc[pp] + cb;
}

extern "C" void kernel_launch(void* const* d_in, const int* in_sizes, int n_in,
                              void* d_out, int out_size) {
    const float* x    = (const float*)d_in[0];
    const float* wK   = (const float*)d_in[1];
    const float* wKs  = (const float*)d_in[2];
    const float* bKs  = (const float*)d_in[3];
    const float* wQ   = (const float*)d_in[4];
    const float* wQs  = (const float*)d_in[5];
    const float* bQs  = (const float*)d_in[6];
    const float* wV   = (const float*)d_in[7];
    const float* wVs  = (const float*)d_in[8];
    const float* bVs  = (const float*)d_in[9];
    const float* wP   = (const float*)d_in[10];
    const float* wPs  = (const float*)d_in[11];
    const float* bPs  = (const float*)d_in[12];
    const float* wM0  = (const float*)d_in[13];
    const float* wM0s = (const float*)d_in[14];
    const float* bM0s = (const float*)d_in[15];
    const float* wM1  = (const float*)d_in[16];
    const float* wM1s = (const float*)d_in[17];
    const float* bM1s = (const float*)d_in[18];
    const float* ng   = (const float*)d_in[19];
    const float* nb   = (const float*)d_in[20];
    float* out = (float*)d_out;

    float *p_xan, *p_F1, *p_F2, *p_R64, *p_k, *p_q, *p_attn;
    float *p_vhat, *p_svhat, *p_ghat, *p_sghat, *p_PF, *p_y2;
    float *p_fno, *p_att, *p_an, *p_m, *p_MF1, *p_MF2;
    cudaGetSymbolAddress((void**)&p_xan,   s_xan);
    cudaGetSymbolAddress((void**)&p_F1,    s_F1);
    cudaGetSymbolAddress((void**)&p_F2,    s_F2);
    cudaGetSymbolAddress((void**)&p_R64,   s_R64);
    cudaGetSymbolAddress((void**)&p_k,     s_k);
    cudaGetSymbolAddress((void**)&p_q,     s_q);
    cudaGetSymbolAddress((void**)&p_attn,  s_attn);
    cudaGetSymbolAddress((void**)&p_vhat,  s_vhat);
    cudaGetSymbolAddress((void**)&p_svhat, s_svhat);
    cudaGetSymbolAddress((void**)&p_ghat,  s_ghat);
    cudaGetSymbolAddress((void**)&p_sghat, s_sghat);
    cudaGetSymbolAddress((void**)&p_PF,    s_PF);
    cudaGetSymbolAddress((void**)&p_y2,    s_y2);
    cudaGetSymbolAddress((void**)&p_fno,   s_fno);
    cudaGetSymbolAddress((void**)&p_att,   s_att);
    cudaGetSymbolAddress((void**)&p_an,    s_an);
    cudaGetSymbolAddress((void**)&p_m,     s_m);
    cudaGetSymbolAddress((void**)&p_MF1,   s_MF1);
    cudaGetSymbolAddress((void**)&p_MF2,   s_MF2);

    k_init<<<1, 128>>>();

    // xa_n (idx0) + partial spectrum
    k_inorm<<<NI, 512>>>(x, nullptr, p_xan, ng, nb, 0, nullptr);
    k_fwd1<33><<<dim3(NI, 4), 288>>>(p_xan, p_F1);
    k_fwd2<<<dim3(NI, 2), 256>>>(p_F1, p_F2, 33);

    // resampled xa_n 64x64 (shared K/Q skip)
    k_inv2<<<dim3(NI, 2), 512>>>(p_F2, nullptr, p_R64, 33, 64, nullptr);

    // K, Q fully fused
    k_kq<<<dim3(NI, NH), 256>>>(p_F2, wK, p_R64, wKs, bKs, p_k);
    k_kq<<<dim3(NI, NH), 256>>>(p_F2, wQ, p_R64, wQs, bQs, p_q);

    // attention weights
    k_scores<<<64, 256>>>(p_q, p_k, p_attn);

    // mode-space V / attention / projection
    k_vhat<<<dim3(NI, NH), 256>>>(p_F2, wV, wVs, bVs, p_vhat, p_svhat);
    k_ghat<<<dim3(2, 32, 16), 256>>>(p_attn, p_vhat, p_ghat, 4096);
    k_ghat<<<dim3(2, 32, 4), 256>>>(p_attn, p_svhat, p_sghat, 1024);
    k_pf<<<dim3(NI, 8), 256>>>(p_ghat, p_sghat, wP, wPs, p_PF);
    k_tokmix<<<dim3(2, 64), 256>>>(p_attn, p_xan, wPs, wVs, bVs, bPs, p_y2);
    k_inv2<<<dim3(NI, 4), 512>>>(p_PF, nullptr, p_fno, 32, 128, p_y2);

    // att = IN1(projd + xa); an = IN2(att)  (fused)
    k_norm12<<<NI, 512>>>(p_fno, x, p_att, p_an, ng, nb);

    // mixer layer 0 (idx3 + gelu)
    k_fwd1<32><<<dim3(NI, 4), 256>>>(p_an, p_MF1);
    k_fwd2<<<dim3(NI, 2), 256>>>(p_MF1, p_MF2, 32);
    k_inv2<<<dim3(NI, 4), 512>>>(p_MF2, wM0, p_fno, 32, 128, nullptr);
    k_normeps<<<NI, 512>>>(p_fno, p_an, p_m, ng, nb, 3, wM0s, bM0s, 1);

    // mixer layer 1 (idx4)
    k_fwd1<32><<<dim3(NI, 4), 256>>>(p_m, p_MF1);
    k_fwd2<<<dim3(NI, 2), 256>>>(p_MF1, p_MF2, 32);
    k_inv2<<<dim3(NI, 4), 512>>>(p_MF2, wM1, p_fno, 32, 128, nullptr);
    k_normeps<<<NI, 512>>>(p_fno, p_m, p_m, ng, nb, 4, wM1s, bM1s, 0);

    // output = IN5(m) + att
    k_inorm<<<NI, 512>>>(p_m, nullptr, out, ng, nb, 5, p_att);
}

// round 9
// speedup vs baseline: 5.3754x; 1.0218x over previous
#include <cuda_runtime.h>
#include <cuda_bf16.h>
#include <cstdint>
#include <cstddef>

#define NI 64
#define NH 32
#define HW 16384

__device__ float d_c[128];
__device__ float d_s[128];

__device__ float s_xan [NI*HW];
__device__ float s_F1  [NI*128*33*2];
__device__ float s_F2  [NI*64*33*2];
__device__ float s_R64 [NI*64*64];
__device__ float s_k   [(size_t)NI*NH*64*64];
__device__ float s_q   [(size_t)NI*NH*64*64];
__device__ float s_attn[64*1024];
__device__ float s_vhat [(size_t)NI*NH*4096];
__device__ float s_svhat[(size_t)NI*NH*1024];
__device__ float s_sghat[(size_t)NI*NH*1024];
__device__ float s_PFp [(size_t)8*NI*4096];
__device__ float s_y2  [NI*HW];
__device__ float s_fno [NI*HW];
__device__ float s_att [NI*HW];
__device__ float s_an  [NI*HW];
__device__ float s_m   [NI*HW];
__device__ float s_MF1 [NI*128*32*2];
__device__ float s_MF2 [NI*64*32*2];

__device__ __forceinline__ void load_tables(float* cs, float* ss) {
    for (int t = threadIdx.x; t < 128; t += blockDim.x) { cs[t] = d_c[t]; ss[t] = d_s[t]; }
}

__global__ void k_init() {
    int k = threadIdx.x;
    d_c[k] = cospif(k / 64.0f);
    d_s[k] = sinpif(k / 64.0f);
}

// -------- instance norm; optional pre-add & post-add
__global__ void k_inorm(const float* __restrict__ src, const float* __restrict__ add,
                        float* __restrict__ dst, const float* __restrict__ gA,
                        const float* __restrict__ bA, int gi, const float* __restrict__ post) {
    int img = blockIdx.x, tid = threadIdx.x;
    const float* s = src + (size_t)img * HW;
    const float* a = add ? add + (size_t)img * HW : nullptr;
    float sum = 0.f, sq = 0.f;
    for (int p = tid; p < HW; p += 512) {
        float v = s[p]; if (a) v += a[p];
        sum += v; sq += v * v;
    }
    __shared__ float r1[512], r2[512];
    r1[tid] = sum; r2[tid] = sq; __syncthreads();
    for (int st = 256; st > 0; st >>= 1) {
        if (tid < st) { r1[tid] += r1[tid + st]; r2[tid] += r2[tid + st]; }
        __syncthreads();
    }
    __shared__ float mean_s, istd_s;
    if (tid == 0) {
        float m = r1[0] * (1.f / HW);
        float var = r2[0] * (1.f / HW) - m * m;
        mean_s = m; istd_s = rsqrtf(var + 1e-5f);
    }
    __syncthreads();
    float g = gA[gi], bb = bA[gi], m = mean_s, is = istd_s;
    for (int p = tid; p < HW; p += 512) {
        float v = s[p]; if (a) v += a[p];
        float r = (v - m) * is * g + bb;
        if (post) r += post[(size_t)img * HW + p];
        dst[(size_t)img * HW + p] = r;
    }
}

// -------- fused IN1(fno+x) -> att, IN2(att) -> an
__global__ void k_norm12(const float* __restrict__ fno, const float* __restrict__ x,
                         float* __restrict__ att, float* __restrict__ an,
                         const float* __restrict__ gA, const float* __restrict__ bA) {
    int img = blockIdx.x, tid = threadIdx.x;
    const float* f = fno + (size_t)img * HW;
    const float* xx = x + (size_t)img * HW;
    float sum = 0.f, sq = 0.f;
    for (int p = tid; p < HW; p += 512) {
        float v = f[p] + xx[p];
        sum += v; sq += v * v;
    }
    __shared__ float r1[512], r2[512];
    r1[tid] = sum; r2[tid] = sq; __syncthreads();
    for (int st = 256; st > 0; st >>= 1) {
        if (tid < st) { r1[tid] += r1[tid + st]; r2[tid] += r2[tid + st]; }
        __syncthreads();
    }
    __shared__ float mean_s, istd_s, istd2_s;
    if (tid == 0) {
        float m = r1[0] * (1.f / HW);
        float var = r2[0] * (1.f / HW) - m * m;
        float is1 = rsqrtf(var + 1e-5f);
        float g1 = gA[1];
        float varatt = g1 * g1 * var * is1 * is1;
        mean_s = m; istd_s = is1;
        istd2_s = rsqrtf(varatt + 1e-5f);
    }
    __syncthreads();
    float g1 = gA[1], b1 = bA[1], g2 = gA[2], b2 = bA[2];
    float m = mean_s, is1 = istd_s, is2 = istd2_s;
    for (int p = tid; p < HW; p += 512) {
        float v = f[p] + xx[p];
        float a = (v - m) * is1 * g1 + b1;
        att[(size_t)img * HW + p] = a;
        an[(size_t)img * HW + p] = (a - b1) * is2 * g2 + b2;
    }
}

// -------- fused IN(gi)(src) then dst = [gelu](norm + ws*src2 + bs)
__global__ void k_normeps(const float* __restrict__ src, const float* __restrict__ src2,
                          float* __restrict__ dst, const float* __restrict__ gA,
                          const float* __restrict__ bA, int gi,
                          const float* __restrict__ ws, const float* __restrict__ bs,
                          int dogelu) {
    int img = blockIdx.x, tid = threadIdx.x;
    const float* s = src + (size_t)img * HW;
    float sum = 0.f, sq = 0.f;
    for (int p = tid; p < HW; p += 512) {
        float v = s[p]; sum += v; sq += v * v;
    }
    __shared__ float r1[512], r2[512];
    r1[tid] = sum; r2[tid] = sq; __syncthreads();
    for (int st = 256; st > 0; st >>= 1) {
        if (tid < st) { r1[tid] += r1[tid + st]; r2[tid] += r2[tid + st]; }
        __syncthreads();
    }
    __shared__ float mean_s, istd_s;
    if (tid == 0) {
        float m = r1[0] * (1.f / HW);
        float var = r2[0] * (1.f / HW) - m * m;
        mean_s = m; istd_s = rsqrtf(var + 1e-5f);
    }
    __syncthreads();
    float g = gA[gi], bb = bA[gi], m = mean_s, is = istd_s;
    float wsv = ws[0], bsv = bs[0];
    for (int p = tid; p < HW; p += 512) {
        float v = (s[p] - m) * is * g + bb + wsv * src2[(size_t)img * HW + p] + bsv;
        if (dogelu) v = 0.5f * v * (1.f + erff(v * 0.70710678118654752f));
        dst[(size_t)img * HW + p] = v;
    }
}

// -------- fwd partial DFT stage1 (cols); 4-row batching
template <int NC>
__global__ void k_fwd1(const float* __restrict__ x, float* __restrict__ out) {
    int n = blockIdx.x, hb = blockIdx.y;
    __shared__ float xs[32 * 128];
    __shared__ float cs[128], ss[128];
    load_tables(cs, ss);
    for (int t = threadIdx.x; t < 32 * 128; t += blockDim.x)
        xs[t] = x[((size_t)n * 128 + hb * 32) * 128 + t];
    __syncthreads();
    int t = threadIdx.x;
    if (t >= 8 * NC) return;
    int hg = t / NC, c = t % NC;
    float rr[4] = {0, 0, 0, 0}, ii[4] = {0, 0, 0, 0};
    int idx = 0;
    #pragma unroll 4
    for (int w = 0; w < 128; w++) {
        float tc = cs[idx], tsn = ss[idx];
        #pragma unroll
        for (int kk = 0; kk < 4; kk++) {
            float v = xs[(hg * 4 + kk) * 128 + w];
            rr[kk] += v * tc; ii[kk] -= v * tsn;
        }
        idx = (idx + c) & 127;
    }
    #pragma unroll
    for (int kk = 0; kk < 4; kk++) {
        int row = hb * 32 + hg * 4 + kk;
        size_t o = ((size_t)(n * 128 + row) * NC + c) * 2;
        out[o] = rr[kk] * (1.f / 128.f); out[o + 1] = ii[kk] * (1.f / 128.f);
    }
}

// -------- fwd stage2 (rows); 4-col batching; split jr over gridDim.y
__global__ void k_fwd2(const float* __restrict__ F1, float* __restrict__ F2o, int NC) {
    int n = blockIdx.x;
    int S = gridDim.y, jrchunk = 64 / S, jr0 = blockIdx.y * jrchunk;
    __shared__ float fs[128 * 33 * 2];
    __shared__ float cs[128], ss[128];
    load_tables(cs, ss);
    int tot = 128 * NC * 2;
    for (int t = threadIdx.x; t < tot; t += blockDim.x)
        fs[t] = F1[(size_t)n * tot + t];
    __syncthreads();
    int CG = (NC + 3) >> 2;
    for (int t = threadIdx.x; t < jrchunk * CG; t += blockDim.x) {
        int jl = t / CG, cg = t % CG;
        int jr = jr0 + jl, c0 = cg * 4;
        int r = jr < 32 ? jr : jr + 64;
        float rr_[4] = {0, 0, 0, 0}, ii_[4] = {0, 0, 0, 0};
        int idx = 0;
        #pragma unroll 4
        for (int h = 0; h < 128; h++) {
            float tc = cs[idx], tsn = ss[idx];
            #pragma unroll
            for (int cc = 0; cc < 4; cc++) {
                if (c0 + cc < NC) {
                    float ar = fs[(h * NC + c0 + cc) * 2], ai = fs[(h * NC + c0 + cc) * 2 + 1];
                    rr_[cc] += ar * tc + ai * tsn;
                    ii_[cc] += ai * tc - ar * tsn;
                }
            }
            idx = (idx + r) & 127;
        }
        #pragma unroll
        for (int cc = 0; cc < 4; cc++) {
            if (c0 + cc < NC) {
                size_t oo = ((size_t)(n * 64 + jr) * NC + c0 + cc) * 2;
                F2o[oo] = rr_[cc] * (1.f / 128.f); F2o[oo + 1] = ii_[cc] * (1.f / 128.f);
            }
        }
    }
}

// -------- fused inverse (row+col), optional weight multiply, partial-sum input, pixel add
__global__ void k_inv2(const float* __restrict__ src, const float* __restrict__ wmul,
                       float* __restrict__ dst, int NC, int P, const float* __restrict__ yadd,
                       int nparts, size_t pstride) {
    int n = blockIdx.x;
    int ybase = blockIdx.y * 32;
    __shared__ float fs[64 * 33 * 2];
    __shared__ float rr[32 * 33 * 2];
    __shared__ float cs[128], ss[128];
    load_tables(cs, ss);
    for (int t = threadIdx.x; t < 64 * NC; t += blockDim.x) {
        int jj = t / NC, c = t % NC;
        size_t base = ((size_t)n * 64 * NC + t) * 2;
        float ar = 0.f, ai = 0.f;
        for (int p = 0; p < nparts; p++) {
            ar += src[p * pstride + base];
            ai += src[p * pstride + base + 1];
        }
        if (wmul) {
            int sgn = jj < 32 ? 0 : 1, jjm = jj & 31;
            const float* wp = wmul + (((size_t)sgn * 32 + jjm) * 32 + c) * 2;
            float wr = wp[0], wi = wp[1];
            float r2 = ar * wr - ai * wi, i2 = ar * wi + ai * wr;
            ar = r2; ai = i2;
        }
        fs[t * 2] = ar; fs[t * 2 + 1] = ai;
    }
    __syncthreads();
    int step = 128 / P;
    int CG = (NC + 3) >> 2;
    for (int t = threadIdx.x; t < 32 * CG; t += blockDim.x) {
        int yl = t / CG, cg = t % CG;
        int y = ybase + yl, c0 = cg * 4;
        float accr[4] = {0, 0, 0, 0}, acci[4] = {0, 0, 0, 0};
        #pragma unroll 4
        for (int jr = 0; jr < 64; jr++) {
            int bin = jr < 32 ? jr : jr + (P - 64);
            int idx = (bin * y * step) & 127;
            float tc = cs[idx], tsn = ss[idx];
            #pragma unroll
            for (int cc = 0; cc < 4; cc++) {
                if (c0 + cc < NC) {
                    float ar = fs[(jr * NC + c0 + cc) * 2], ai = fs[(jr * NC + c0 + cc) * 2 + 1];
                    accr[cc] += ar * tc - ai * tsn;
                    acci[cc] += ar * tsn + ai * tc;
                }
            }
        }
        #pragma unroll
        for (int cc = 0; cc < 4; cc++) {
            if (c0 + cc < NC) {
                rr[(yl * NC + c0 + cc) * 2] = accr[cc];
                rr[(yl * NC + c0 + cc) * 2 + 1] = acci[cc];
            }
        }
    }
    __syncthreads();
    int nyq = ((NC - 1) * 2 == P) ? 1 : 0;
    int cmax = nyq ? NC - 1 : NC;
    int PP = P * P;
    int slots = 8 * P;
    for (int t = threadIdx.x; t < slots; t += blockDim.x) {
        int x = t % P, yg = t / P;
        int yl0 = yg * 4;
        float acc[4];
        #pragma unroll
        for (int yy = 0; yy < 4; yy++) acc[yy] = rr[((yl0 + yy) * NC) * 2];
        #pragma unroll 4
        for (int c = 1; c < cmax; c++) {
            int idx = (c * x * step) & 127;
            float tc = cs[idx], tsn = ss[idx];
            #pragma unroll
            for (int yy = 0; yy < 4; yy++) {
                float re = rr[((yl0 + yy) * NC + c) * 2], im = rr[((yl0 + yy) * NC + c) * 2 + 1];
                acc[yy] += 2.f * (re * tc - im * tsn);
            }
        }
        if (nyq) {
            int idx = ((NC - 1) * x * step) & 127;
            float tc = cs[idx];
            #pragma unroll
            for (int yy = 0; yy < 4; yy++)
                acc[yy] += rr[((yl0 + yy) * NC + NC - 1) * 2] * tc;
        }
        #pragma unroll
        for (int yy = 0; yy < 4; yy++) {
            int p = (ybase + yl0 + yy) * P + x;
            float v = acc[yy];
            if (yadd) v += yadd[(size_t)n * PP + p];
            dst[(size_t)n * PP + p] = v;
        }
    }
}

// -------- K/Q fused (z=0 -> K, z=1 -> Q)
__global__ void k_kq(const float* __restrict__ F2src,
                     const float* __restrict__ wKp, const float* __restrict__ wQp,
                     const float* __restrict__ R64,
                     const float* __restrict__ wsK, const float* __restrict__ bsK,
                     const float* __restrict__ wsQ, const float* __restrict__ bsQ,
                     float* __restrict__ dstK, float* __restrict__ dstQ) {
    int i = blockIdx.x, o = blockIdx.y, z = blockIdx.z;
    const float* w = z ? wQp : wKp;
    const float* ws = z ? wsQ : wsK;
    const float* bs = z ? bsQ : bsK;
    float* dst = z ? dstQ : dstK;
    __shared__ float fw[32 * 16 * 2];
    __shared__ float rr[64 * 16 * 2];
    __shared__ float cs[128], ss[128];
    load_tables(cs, ss);
    for (int t = threadIdx.x; t < 512; t += blockDim.x) {
        int jj = t >> 4, c = t & 15;
        int jr = jj < 16 ? jj : jj + 32;
        int sgn = jj < 16 ? 0 : 1, jjm = jj & 15;
        float ar = F2src[((size_t)(i * 64 + jr) * 33 + c) * 2];
        float ai = F2src[((size_t)(i * 64 + jr) * 33 + c) * 2 + 1];
        const float* wp = w + (((size_t)(sgn * 32 + o) * 16 + jjm) * 16 + c) * 2;
        float wr = wp[0], wi = wp[1];
        fw[t * 2]     = ar * wr - ai * wi;
        fw[t * 2 + 1] = ar * wi + ai * wr;
    }
    __syncthreads();
    for (int t = threadIdx.x; t < 1024; t += blockDim.x) {
        int y = t >> 4, c = t & 15;
        float re = 0.f, im = 0.f;
        #pragma unroll
        for (int jj = 0; jj < 32; jj++) {
            int bin = jj < 16 ? jj : jj + 32;
            int idx = (bin * y * 2) & 127;
            float ar = fw[(jj * 16 + c) * 2], ai = fw[(jj * 16 + c) * 2 + 1];
            re += ar * cs[idx] - ai * ss[idx];
            im += ar * ss[idx] + ai * cs[idx];
        }
        rr[t * 2] = re; rr[t * 2 + 1] = im;
    }
    __syncthreads();
    float wsv = ws[o], bsv = bs[o];
    size_t obase = (size_t)(i * 32 + o) * 4096;
    for (int t = threadIdx.x; t < 1024; t += blockDim.x) {
        int x = t & 63, yg = t >> 6;
        int y0 = yg * 4;
        float acc[4];
        #pragma unroll
        for (int yy = 0; yy < 4; yy++) acc[yy] = rr[((y0 + yy) * 16) * 2];
        #pragma unroll
        for (int c = 1; c < 16; c++) {
            int idx = (c * x * 2) & 127;
            float tc = cs[idx], tsn = ss[idx];
            #pragma unroll
            for (int yy = 0; yy < 4; yy++) {
                float re = rr[((y0 + yy) * 16 + c) * 2], im = rr[((y0 + yy) * 16 + c) * 2 + 1];
                acc[yy] += 2.f * (re * tc - im * tsn);
            }
        }
        #pragma unroll
        for (int yy = 0; yy < 4; yy++) {
            int p = (y0 + yy) * 64 + x;
            dst[obase + p] = acc[yy] + wsv * R64[(size_t)i * 4096 + p] + bsv;
        }
    }
}

// -------- scores + softmax
__global__ void k_scores(const float* __restrict__ q, const float* __restrict__ k,
                         float* __restrict__ attn) {
    int bh = blockIdx.x, b = bh >> 5, h = bh & 31;
    int tid = threadIdx.x;
    int ti = tid >> 4, si = tid & 15;
    __shared__ float qs_[32 * 132], ks_[32 * 132];
    float a00 = 0.f, a01 = 0.f, a10 = 0.f, a11 = 0.f;
    for (int kk = 0; kk < 4096; kk += 128) {
        __syncthreads();
        for (int t = tid; t < 4096; t += 256) {
            int row = t >> 7, col = t & 127;
            size_t base = (size_t)((b * 32 + row) * 32 + h) * 4096 + kk + col;
            qs_[row * 132 + col] = q[base];
            ks_[row * 132 + col] = k[base];
        }
        __syncthreads();
        #pragma unroll 4
        for (int j = 0; j < 128; j++) {
            float q0 = qs_[(2 * ti) * 132 + j], q1 = qs_[(2 * ti + 1) * 132 + j];
            float k0 = ks_[(2 * si) * 132 + j], k1 = ks_[(2 * si + 1) * 132 + j];
            a00 += q0 * k0; a01 += q0 * k1; a10 += q1 * k0; a11 += q1 * k1;
        }
    }
    float sc = 1.f / 64.f;
    a00 *= sc; a01 *= sc; a10 *= sc; a11 *= sc;
    float m0 = fmaxf(a00, a01), m1v = fmaxf(a10, a11);
    for (int o = 8; o > 0; o >>= 1) {
        m0  = fmaxf(m0,  __shfl_xor_sync(0xffffffffu, m0,  o));
        m1v = fmaxf(m1v, __shfl_xor_sync(0xffffffffu, m1v, o));
    }
    float e00 = expf(a00 - m0), e01 = expf(a01 - m0);
    float e10 = expf(a10 - m1v), e11 = expf(a11 - m1v);
    float s0 = e00 + e01, s1 = e10 + e11;
    for (int o = 8; o > 0; o >>= 1) {
        s0 += __shfl_xor_sync(0xffffffffu, s0, o);
        s1 += __shfl_xor_sync(0xffffffffu, s1, o);
    }
    float* ap = attn + (size_t)bh * 1024;
    ap[(2 * ti) * 32 + 2 * si]         = e00 / s0;
    ap[(2 * ti) * 32 + 2 * si + 1]     = e01 / s0;
    ap[(2 * ti + 1) * 32 + 2 * si]     = e10 / s1;
    ap[(2 * ti + 1) * 32 + 2 * si + 1] = e11 / s1;
}

// -------- Vhat + SpecVhat
__global__ void k_vhat(const float* __restrict__ F2, const float* __restrict__ wV,
                       const float* __restrict__ wVs, const float* __restrict__ bVs,
                       float* __restrict__ vhat, float* __restrict__ svhat) {
    int i = blockIdx.x, h = blockIdx.y;
    __shared__ float f2s[64 * 33 * 2];
    __shared__ float wv_s[1024];
    for (int t = threadIdx.x; t < 64 * 33 * 2; t += blockDim.x)
        f2s[t] = F2[(size_t)i * (64 * 33 * 2) + t];
    for (int t = threadIdx.x; t < 1024; t += blockDim.x) {
        int sgn = t >> 9;
        wv_s[t] = wV[((size_t)(sgn * 32 + h) * 256) * 2 + (t & 511)];
    }
    __syncthreads();
    float wvsv = wVs[h], bvsv = bVs[h];

    #define OF(JJ, CC, ORR, OII) { int sg_ = (JJ) < 16 ? 0 : 1; int jm_ = (JJ) < 16 ? (JJ) : (JJ) - 48; \
        float fr_ = f2s[((JJ) * 33 + (CC)) * 2], fi_ = f2s[((JJ) * 33 + (CC)) * 2 + 1]; \
        float wr_ = wv_s[sg_ * 512 + (jm_ * 16 + (CC)) * 2], wi_ = wv_s[sg_ * 512 + (jm_ * 16 + (CC)) * 2 + 1]; \
        ORR = fr_ * wr_ - fi_ * wi_; OII = fr_ * wi_ + fi_ * wr_; }

    for (int t = threadIdx.x; t < 2048; t += blockDim.x) {
        int jj = t >> 5, c = t & 31;
        float fr = f2s[(jj * 33 + c) * 2], fi = f2s[(jj * 33 + c) * 2 + 1];
        float vr = wvsv * fr, vi = wvsv * fi;
        if (jj == 0 && c == 0) vr += bvsv;
        if (c >= 1 && c < 16 && (jj < 16 || jj >= 48)) {
            float orr, oii; OF(jj, c, orr, oii);
            vr += orr; vi += oii;
        } else if (c == 0) {
            if (jj == 0) {
                float orr, oii; OF(0, 0, orr, oii); (void)oii;
                vr += orr;
            } else if (jj <= 15) {
                float o1r, o1i, o2r, o2i;
                OF(jj, 0, o1r, o1i); OF(64 - jj, 0, o2r, o2i);
                vr += 0.5f * (o1r + o2r); vi += 0.5f * (o1i - o2i);
            } else if (jj == 16) {
                float orr, oii; OF(48, 0, orr, oii);
                vr += 0.5f * orr; vi -= 0.5f * oii;
            } else if (jj == 48) {
                float orr, oii; OF(48, 0, orr, oii);
                vr += 0.5f * orr; vi += 0.5f * oii;
            } else if (jj >= 49) {
                float o1r, o1i, o2r, o2i;
                OF(jj, 0, o1r, o1i); OF(64 - jj, 0, o2r, o2i);
                vr += 0.5f * (o1r + o2r); vi += 0.5f * (o1i - o2i);
            }
        }
        size_t oo = ((size_t)(i * 32 + h) * 2048 + t) * 2;
        vhat[oo] = vr; vhat[oo + 1] = vi;
    }
    for (int t = threadIdx.x; t < 512; t += blockDim.x) {
        int jm = t >> 4, c = t & 15;
        int jj = jm < 16 ? jm : jm + 32;
        float orr, oii; OF(jj, c, orr, oii);
        size_t oo = ((size_t)(i * 32 + h) * 512 + t) * 2;
        svhat[oo] = orr; svhat[oo + 1] = oii;
    }
    #undef OF
}

// -------- small ghat for spec window: sghat = attn x svhat
__global__ void k_ghat(const float* __restrict__ attn, const float* __restrict__ vin,
                       float* __restrict__ gout, int ncols) {
    int b = blockIdx.x, h = blockIdx.y, c0 = blockIdx.z * 256;
    __shared__ float a_sh[1024];
    __shared__ float vs[32 * 256];
    for (int t = threadIdx.x; t < 1024; t += 256)
        a_sh[t] = attn[(size_t)(b * 32 + h) * 1024 + t];
    for (int t = threadIdx.x; t < 8192; t += 256) {
        int s = t >> 8, c = t & 255;
        vs[t] = vin[(size_t)((b * 32 + s) * 32 + h) * ncols + c0 + c];
    }
    __syncthreads();
    int tq = threadIdx.x >> 5;
    int cg = threadIdx.x & 31;
    float acc[4][8];
    #pragma unroll
    for (int r = 0; r < 4; r++)
        #pragma unroll
        for (int cc = 0; cc < 8; cc++) acc[r][cc] = 0.f;
    for (int s = 0; s < 32; s++) {
        float a0 = a_sh[(tq * 4 + 0) * 32 + s];
        float a1 = a_sh[(tq * 4 + 1) * 32 + s];
        float a2 = a_sh[(tq * 4 + 2) * 32 + s];
        float a3 = a_sh[(tq * 4 + 3) * 32 + s];
        const float* vp = vs + s * 256 + cg * 8;
        #pragma unroll
        for (int cc = 0; cc < 8; cc++) {
            float v = vp[cc];
            acc[0][cc] += a0 * v; acc[1][cc] += a1 * v;
            acc[2][cc] += a2 * v; acc[3][cc] += a3 * v;
        }
    }
    #pragma unroll
    for (int r = 0; r < 4; r++)
        #pragma unroll
        for (int cc = 0; cc < 8; cc++)
            gout[(size_t)((b * 32 + tq * 4 + r) * 32 + h) * ncols + c0 + cg * 8 + cc] = acc[r][cc];
}

// -------- fused (attn x vhat) x wP -> PF partials; grid (b=2, mc=16, hg=8)
__global__ void k_gpf(const float* __restrict__ attn, const float* __restrict__ vhat,
                      const float* __restrict__ wP, float* __restrict__ PFp) {
    int b = blockIdx.x, mc = blockIdx.y, hg = blockIdx.z;
    __shared__ float a_sh[1024];
    __shared__ float vs[8192];
    int tid = threadIdx.x;
    int tq = tid >> 5, mg = tid & 31;
    float accr[4][4], acci[4][4];
    #pragma unroll
    for (int r = 0; r < 4; r++)
        #pragma unroll
        for (int m = 0; m < 4; m++) { accr[r][m] = 0.f; acci[r][m] = 0.f; }
    for (int hh = 0; hh < 4; hh++) {
        int h = hg * 4 + hh;
        __syncthreads();
        for (int t = tid; t < 1024; t += 256)
            a_sh[t] = attn[(size_t)(b * 32 + h) * 1024 + t];
        for (int t = tid; t < 8192; t += 256) {
            int s = t >> 8, c = t & 255;
            vs[t] = vhat[((size_t)((b * 32 + s) * 32 + h) * 2048 + mc * 128) * 2 + c];
        }
        __syncthreads();
        float tr[4][4], ti_[4][4];
        #pragma unroll
        for (int r = 0; r < 4; r++)
            #pragma unroll
            for (int m = 0; m < 4; m++) { tr[r][m] = 0.f; ti_[r][m] = 0.f; }
        #pragma unroll 4
        for (int s = 0; s < 32; s++) {
            float a0 = a_sh[(tq * 4 + 0) * 32 + s];
            float a1 = a_sh[(tq * 4 + 1) * 32 + s];
            float a2 = a_sh[(tq * 4 + 2) * 32 + s];
            float a3 = a_sh[(tq * 4 + 3) * 32 + s];
            const float* vp = vs + s * 256 + mg * 8;
            #pragma unroll
            for (int m = 0; m < 4; m++) {
                float vre = vp[m * 2], vim = vp[m * 2 + 1];
                tr[0][m] += a0 * vre; ti_[0][m] += a0 * vim;
                tr[1][m] += a1 * vre; ti_[1][m] += a1 * vim;
                tr[2][m] += a2 * vre; ti_[2][m] += a2 * vim;
                tr[3][m] += a3 * vre; ti_[3][m] += a3 * vim;
            }
        }
        #pragma unroll
        for (int m = 0; m < 4; m++) {
            int M = mc * 128 + mg * 4 + m;
            int jj = M >> 5, c = M & 31;
            int sgn = jj < 32 ? 0 : 1, jjm = jj & 31;
            const float* wp = wP + (((size_t)(sgn * 32 + h) * 32 + jjm) * 32 + c) * 2;
            float wr = wp[0], wi = wp[1];
            #pragma unroll
            for (int r = 0; r < 4; r++) {
                accr[r][m] += tr[r][m] * wr - ti_[r][m] * wi;
                acci[r][m] += tr[r][m] * wi + ti_[r][m] * wr;
            }
        }
    }
    #pragma unroll
    for (int r = 0; r < 4; r++) {
        int i = b * 32 + tq * 4 + r;
        #pragma unroll
        for (int m = 0; m < 4; m++) {
            int M = mc * 128 + mg * 4 + m;
            size_t o = (size_t)hg * (NI * 4096) + (size_t)i * 4096 + (size_t)M * 2;
            PFp[o] = accr[r][m]; PFp[o + 1] = acci[r][m];
        }
    }
}

// -------- window extras into PF partial slot 0
__global__ void k_pfw(const float* __restrict__ sghat, const float* __restrict__ wPs,
                      float* __restrict__ PFp) {
    int i = blockIdx.x;
    int w = blockIdx.y * 256 + threadIdx.x;
    __shared__ float wps_[32];
    if (threadIdx.x < 32) wps_[threadIdx.x] = wPs[threadIdx.x];
    __syncthreads();
    int jm = w >> 4, c = w & 15;
    int jj = jm < 16 ? jm : jm + 32;
    int t = jj * 32 + c;
    float re = 0.f, im = 0.f;
    #pragma unroll 4
    for (int h = 0; h < 32; h++) {
        const float* sg = sghat + ((size_t)(i * 32 + h) * 512 + w) * 2;
        re += wps_[h] * sg[0]; im += wps_[h] * sg[1];
    }
    size_t o = (size_t)i * 4096 + (size_t)t * 2;
    PFp[o] += re; PFp[o + 1] += im;
}

// -------- token mix y2
__global__ void k_tokmix(const float* __restrict__ attn, const float* __restrict__ xan,
                         const float* __restrict__ wPs, const float* __restrict__ wVs,
                         const float* __restrict__ bVs, const float* __restrict__ bPs,
                         float* __restrict__ y2) {
    int b = blockIdx.x;
    int pbase = blockIdx.y * 256;
    int tid = threadIdx.x;
    __shared__ float C[1024];
    __shared__ float xs[32 * 256];
    __shared__ float cb_s;
    {
        int t = tid >> 3, s0 = (tid & 7) * 4;
        float c0 = 0.f, c1 = 0.f, c2 = 0.f, c3 = 0.f;
        for (int h = 0; h < 32; h++) {
            float w = wPs[h] * wVs[h];
            const float* ap = attn + (size_t)(b * 32 + h) * 1024 + t * 32 + s0;
            c0 += w * ap[0]; c1 += w * ap[1]; c2 += w * ap[2]; c3 += w * ap[3];
        }
        C[t * 32 + s0] = c0; C[t * 32 + s0 + 1] = c1;
        C[t * 32 + s0 + 2] = c2; C[t * 32 + s0 + 3] = c3;
    }
    if (tid == 0) {
        float cb = bPs[0];
        for (int h = 0; h < 32; h++) cb += wPs[h] * bVs[h];
        cb_s = cb;
    }
    for (int t = tid; t < 8192; t += 256) {
        int s = t >> 8, c = t & 255;
        xs[t] = xan[(size_t)(b * 32 + s) * HW + pbase + c];
    }
    __syncthreads();
    int t = tid >> 3, pg = tid & 7;
    float acc[32];
    #pragma unroll
    for (int pp = 0; pp < 32; pp++) acc[pp] = 0.f;
    for (int s = 0; s < 32; s++) {
        float cc = C[t * 32 + s];
        const float* xp = xs + s * 256 + pg * 32;
        #pragma unroll
        for (int pp = 0; pp < 32; pp++) acc[pp] += cc * xp[pp];
    }
    float cb = cb_s;
    #pragma unroll
    for (int pp = 0; pp < 32; pp++)
        y2[(size_t)(b * 32 + t) * HW + pbase + pg * 32 + pp] = acc[pp] + cb;
}

extern "C" void kernel_launch(void* const* d_in, const int* in_sizes, int n_in,
                              void* d_out, int out_size) {
    const float* x    = (const float*)d_in[0];
    const float* wK   = (const float*)d_in[1];
    const float* wKs  = (const float*)d_in[2];
    const float* bKs  = (const float*)d_in[3];
    const float* wQ   = (const float*)d_in[4];
    const float* wQs  = (const float*)d_in[5];
    const float* bQs  = (const float*)d_in[6];
    const float* wV   = (const float*)d_in[7];
    const float* wVs  = (const float*)d_in[8];
    const float* bVs  = (const float*)d_in[9];
    const float* wP   = (const float*)d_in[10];
    const float* wPs  = (const float*)d_in[11];
    const float* bPs  = (const float*)d_in[12];
    const float* wM0  = (const float*)d_in[13];
    const float* wM0s = (const float*)d_in[14];
    const float* bM0s = (const float*)d_in[15];
    const float* wM1  = (const float*)d_in[16];
    const float* wM1s = (const float*)d_in[17];
    const float* bM1s = (const float*)d_in[18];
    const float* ng   = (const float*)d_in[19];
    const float* nb   = (const float*)d_in[20];
    float* out = (float*)d_out;

    float *p_xan, *p_F1, *p_F2, *p_R64, *p_k, *p_q, *p_attn;
    float *p_vhat, *p_svhat, *p_sghat, *p_PFp, *p_y2;
    float *p_fno, *p_att, *p_an, *p_m, *p_MF1, *p_MF2;
    cudaGetSymbolAddress((void**)&p_xan,   s_xan);
    cudaGetSymbolAddress((void**)&p_F1,    s_F1);
    cudaGetSymbolAddress((void**)&p_F2,    s_F2);
    cudaGetSymbolAddress((void**)&p_R64,   s_R64);
    cudaGetSymbolAddress((void**)&p_k,     s_k);
    cudaGetSymbolAddress((void**)&p_q,     s_q);
    cudaGetSymbolAddress((void**)&p_attn,  s_attn);
    cudaGetSymbolAddress((void**)&p_vhat,  s_vhat);
    cudaGetSymbolAddress((void**)&p_svhat, s_svhat);
    cudaGetSymbolAddress((void**)&p_sghat, s_sghat);
    cudaGetSymbolAddress((void**)&p_PFp,   s_PFp);
    cudaGetSymbolAddress((void**)&p_y2,    s_y2);
    cudaGetSymbolAddress((void**)&p_fno,   s_fno);
    cudaGetSymbolAddress((void**)&p_att,   s_att);
    cudaGetSymbolAddress((void**)&p_an,    s_an);
    cudaGetSymbolAddress((void**)&p_m,     s_m);
    cudaGetSymbolAddress((void**)&p_MF1,   s_MF1);
    cudaGetSymbolAddress((void**)&p_MF2,   s_MF2);

    const size_t PSTRIDE = (size_t)NI * 4096;

    k_init<<<1, 128>>>();

    // xa_n (idx0) + partial spectrum
    k_inorm<<<NI, 512>>>(x, nullptr, p_xan, ng, nb, 0, nullptr);
    k_fwd1<33><<<dim3(NI, 4), 288>>>(p_xan, p_F1);
    k_fwd2<<<dim3(NI, 4), 256>>>(p_F1, p_F2, 33);

    // resampled xa_n 64x64
    k_inv2<<<dim3(NI, 2), 512>>>(p_F2, nullptr, p_R64, 33, 64, nullptr, 1, 0);

    // K + Q fused
    k_kq<<<dim3(NI, NH, 2), 256>>>(p_F2, wK, wQ, p_R64, wKs, bKs, wQs, bQs, p_k, p_q);

    // attention weights
    k_scores<<<64, 256>>>(p_q, p_k, p_attn);

    // mode-space V / attention / projection
    k_vhat<<<dim3(NI, NH), 256>>>(p_F2, wV, wVs, bVs, p_vhat, p_svhat);
    k_ghat<<<dim3(2, 32, 4), 256>>>(p_attn, p_svhat, p_sghat, 1024);
    k_gpf<<<dim3(2, 16, 8), 256>>>(p_attn, p_vhat, wP, p_PFp);
    k_pfw<<<dim3(NI, 2), 256>>>(p_sghat, wPs, p_PFp);
    k_tokmix<<<dim3(2, 64), 256>>>(p_attn, p_xan, wPs, wVs, bVs, bPs, p_y2);
    k_inv2<<<dim3(NI, 4), 512>>>(p_PFp, nullptr, p_fno, 32, 128, p_y2, 8, PSTRIDE);

    // att = IN1(projd + xa); an = IN2(att)
    k_norm12<<<NI, 512>>>(p_fno, x, p_att, p_an, ng, nb);

    // mixer layer 0 (idx3 + gelu)
    k_fwd1<32><<<dim3(NI, 4), 256>>>(p_an, p_MF1);
    k_fwd2<<<dim3(NI, 4), 256>>>(p_MF1, p_MF2, 32);
    k_inv2<<<dim3(NI, 4), 512>>>(p_MF2, wM0, p_fno, 32, 128, nullptr, 1, 0);
    k_normeps<<<NI, 512>>>(p_fno, p_an, p_m, ng, nb, 3, wM0s, bM0s, 1);

    // mixer layer 1 (idx4)
    k_fwd1<32><<<dim3(NI, 4), 256>>>(p_m, p_MF1);
    k_fwd2<<<dim3(NI, 4), 256>>>(p_MF1, p_MF2, 32);
    k_inv2<<<dim3(NI, 4), 512>>>(p_MF2, wM1, p_fno, 32, 128, nullptr, 1, 0);
    k_normeps<<<NI, 512>>>(p_fno, p_m, p_m, ng, nb, 4, wM1s, bM1s, 0);

    // output = IN5(m) + att
    k_inorm<<<NI, 512>>>(p_m, nullptr, out, ng, nb, 5, p_att);
}

// round 10
// speedup vs baseline: 7.6462x; 1.4225x over previous
#include <cuda_runtime.h>
#include <cuda_bf16.h>
#include <cstdint>
#include <cstddef>

#define NI 64
#define NH 32
#define HW 16384

__device__ float d_c[128];
__device__ float d_s[128];

__device__ float s_xan [NI*HW];
__device__ float s_F1  [NI*128*33*2];
__device__ float s_F2  [NI*64*33*2];
__device__ float s_R64 [NI*64*64];
__device__ float s_k   [(size_t)NI*NH*64*64];
__device__ float s_q   [(size_t)NI*NH*64*64];
__device__ float s_scp [8*64*1024];
__device__ float s_attn[64*1024];
__device__ float s_vhat [(size_t)NI*NH*4096];
__device__ float s_svhat[(size_t)NI*NH*1024];
__device__ float s_sghat[(size_t)NI*NH*1024];
__device__ float s_PFp [(size_t)8*NI*4096];
__device__ float s_y2  [NI*HW];
__device__ float s_fno [NI*HW];
__device__ float s_att [NI*HW];
__device__ float s_an  [NI*HW];
__device__ float s_m   [NI*HW];
__device__ float s_MF1 [NI*128*32*2];
__device__ float s_MF2 [NI*64*32*2];

__device__ __forceinline__ void load_tables(float* cs, float* ss) {
    for (int t = threadIdx.x; t < 128; t += blockDim.x) { cs[t] = d_c[t]; ss[t] = d_s[t]; }
}

__global__ void k_init() {
    int k = threadIdx.x;
    d_c[k] = cospif(k / 64.0f);
    d_s[k] = sinpif(k / 64.0f);
}

// -------- instance norm (1024 thr); optional pre-add & post-add
__global__ void k_inorm(const float* __restrict__ src, const float* __restrict__ add,
                        float* __restrict__ dst, const float* __restrict__ gA,
                        const float* __restrict__ bA, int gi, const float* __restrict__ post) {
    int img = blockIdx.x, tid = threadIdx.x;
    const float* s = src + (size_t)img * HW;
    const float* a = add ? add + (size_t)img * HW : nullptr;
    float sum = 0.f, sq = 0.f;
    for (int p = tid; p < HW; p += 1024) {
        float v = s[p]; if (a) v += a[p];
        sum += v; sq += v * v;
    }
    __shared__ float r1[1024], r2[1024];
    r1[tid] = sum; r2[tid] = sq; __syncthreads();
    for (int st = 512; st > 0; st >>= 1) {
        if (tid < st) { r1[tid] += r1[tid + st]; r2[tid] += r2[tid + st]; }
        __syncthreads();
    }
    __shared__ float mean_s, istd_s;
    if (tid == 0) {
        float m = r1[0] * (1.f / HW);
        float var = r2[0] * (1.f / HW) - m * m;
        mean_s = m; istd_s = rsqrtf(var + 1e-5f);
    }
    __syncthreads();
    float g = gA[gi], bb = bA[gi], m = mean_s, is = istd_s;
    for (int p = tid; p < HW; p += 1024) {
        float v = s[p]; if (a) v += a[p];
        float r = (v - m) * is * g + bb;
        if (post) r += post[(size_t)img * HW + p];
        dst[(size_t)img * HW + p] = r;
    }
}

// -------- fused IN1(fno+x) -> att, IN2(att) -> an
__global__ void k_norm12(const float* __restrict__ fno, const float* __restrict__ x,
                         float* __restrict__ att, float* __restrict__ an,
                         const float* __restrict__ gA, const float* __restrict__ bA) {
    int img = blockIdx.x, tid = threadIdx.x;
    const float* f = fno + (size_t)img * HW;
    const float* xx = x + (size_t)img * HW;
    float sum = 0.f, sq = 0.f;
    for (int p = tid; p < HW; p += 1024) {
        float v = f[p] + xx[p];
        sum += v; sq += v * v;
    }
    __shared__ float r1[1024], r2[1024];
    r1[tid] = sum; r2[tid] = sq; __syncthreads();
    for (int st = 512; st > 0; st >>= 1) {
        if (tid < st) { r1[tid] += r1[tid + st]; r2[tid] += r2[tid + st]; }
        __syncthreads();
    }
    __shared__ float mean_s, istd_s, istd2_s;
    if (tid == 0) {
        float m = r1[0] * (1.f / HW);
        float var = r2[0] * (1.f / HW) - m * m;
        float is1 = rsqrtf(var + 1e-5f);
        float g1 = gA[1];
        float varatt = g1 * g1 * var * is1 * is1;
        mean_s = m; istd_s = is1;
        istd2_s = rsqrtf(varatt + 1e-5f);
    }
    __syncthreads();
    float g1 = gA[1], b1 = bA[1], g2 = gA[2], b2 = bA[2];
    float m = mean_s, is1 = istd_s, is2 = istd2_s;
    for (int p = tid; p < HW; p += 1024) {
        float v = f[p] + xx[p];
        float a = (v - m) * is1 * g1 + b1;
        att[(size_t)img * HW + p] = a;
        an[(size_t)img * HW + p] = (a - b1) * is2 * g2 + b2;
    }
}

// -------- fused IN(gi)(src) then dst = [gelu](norm + ws*src2 + bs)
__global__ void k_normeps(const float* __restrict__ src, const float* __restrict__ src2,
                          float* __restrict__ dst, const float* __restrict__ gA,
                          const float* __restrict__ bA, int gi,
                          const float* __restrict__ ws, const float* __restrict__ bs,
                          int dogelu) {
    int img = blockIdx.x, tid = threadIdx.x;
    const float* s = src + (size_t)img * HW;
    float sum = 0.f, sq = 0.f;
    for (int p = tid; p < HW; p += 1024) {
        float v = s[p]; sum += v; sq += v * v;
    }
    __shared__ float r1[1024], r2[1024];
    r1[tid] = sum; r2[tid] = sq; __syncthreads();
    for (int st = 512; st > 0; st >>= 1) {
        if (tid < st) { r1[tid] += r1[tid + st]; r2[tid] += r2[tid + st]; }
        __syncthreads();
    }
    __shared__ float mean_s, istd_s;
    if (tid == 0) {
        float m = r1[0] * (1.f / HW);
        float var = r2[0] * (1.f / HW) - m * m;
        mean_s = m; istd_s = rsqrtf(var + 1e-5f);
    }
    __syncthreads();
    float g = gA[gi], bb = bA[gi], m = mean_s, is = istd_s;
    float wsv = ws[0], bsv = bs[0];
    for (int p = tid; p < HW; p += 1024) {
        float v = (s[p] - m) * is * g + bb + wsv * src2[(size_t)img * HW + p] + bsv;
        if (dogelu) v = 0.5f * v * (1.f + erff(v * 0.70710678118654752f));
        dst[(size_t)img * HW + p] = v;
    }
}

// -------- fwd stage1 (cols); 4-row batching, twiddle recurrence
template <int NC>
__global__ void k_fwd1(const float* __restrict__ x, float* __restrict__ out) {
    int n = blockIdx.x, hb = blockIdx.y;
    __shared__ float xs[32 * 128];
    __shared__ float cs[128], ss[128];
    load_tables(cs, ss);
    for (int t = threadIdx.x; t < 32 * 128; t += blockDim.x)
        xs[t] = x[((size_t)n * 128 + hb * 32) * 128 + t];
    __syncthreads();
    int t = threadIdx.x;
    if (t >= 8 * NC) return;
    int hg = t / NC, c = t % NC;
    float rr[4] = {0, 0, 0, 0}, ii[4] = {0, 0, 0, 0};
    float wr = 1.f, wi = 0.f;
    float str = cs[c], sti = -ss[c];       // e^{-i 2pi c/128}
    #pragma unroll 4
    for (int w = 0; w < 128; w++) {
        #pragma unroll
        for (int kk = 0; kk < 4; kk++) {
            float v = xs[(hg * 4 + kk) * 128 + w];
            rr[kk] += v * wr; ii[kk] += v * wi;
        }
        float nwr = wr * str - wi * sti;
        wi = wr * sti + wi * str;
        wr = nwr;
    }
    #pragma unroll
    for (int kk = 0; kk < 4; kk++) {
        int row = hb * 32 + hg * 4 + kk;
        size_t o = ((size_t)(n * 128 + row) * NC + c) * 2;
        out[o] = rr[kk] * (1.f / 128.f); out[o + 1] = ii[kk] * (1.f / 128.f);
    }
}

// -------- fwd stage2 (rows); c-chunked, twiddle recurrence; grid (NI, 4)
__global__ void k_fwd2(const float* __restrict__ F1, float* __restrict__ F2o, int NC) {
    int n = blockIdx.x;
    int chunk = (NC + gridDim.y - 1) / gridDim.y;
    int c0 = blockIdx.y * chunk;
    int cn = NC - c0 < chunk ? NC - c0 : chunk;
    __shared__ float fs[128 * 9 * 2];
    __shared__ float cs[128], ss[128];
    load_tables(cs, ss);
    for (int t = threadIdx.x; t < 128 * cn * 2; t += blockDim.x) {
        int h = t / (cn * 2), rem = t % (cn * 2);
        fs[t] = F1[((size_t)(n * 128 + h) * NC + c0) * 2 + rem];
    }
    __syncthreads();
    int tid = threadIdx.x;
    if (tid >= 64 * cn) return;
    int jr = tid / cn, cl = tid % cn;
    int r = jr < 32 ? jr : jr + 64;
    float wr = 1.f, wi = 0.f;
    float str = cs[r & 127], sti = -ss[r & 127];
    float re = 0.f, im = 0.f;
    #pragma unroll 4
    for (int h = 0; h < 128; h++) {
        float ar = fs[(h * cn + cl) * 2], ai = fs[(h * cn + cl) * 2 + 1];
        re += ar * wr - ai * wi;
        im += ar * wi + ai * wr;
        float nwr = wr * str - wi * sti;
        wi = wr * sti + wi * str;
        wr = nwr;
    }
    size_t oo = ((size_t)(n * 64 + jr) * NC + c0 + cl) * 2;
    F2o[oo] = re * (1.f / 128.f); F2o[oo + 1] = im * (1.f / 128.f);
}

// -------- fused inverse (row+col), optional weight mult, partial sums, pixel add; recurrences
__global__ void k_inv2(const float* __restrict__ src, const float* __restrict__ wmul,
                       float* __restrict__ dst, int NC, int P, const float* __restrict__ yadd,
                       int nparts, size_t pstride) {
    int n = blockIdx.x;
    int ybase = blockIdx.y * 32;
    __shared__ float fs[64 * 33 * 2];
    __shared__ float rr[32 * 33 * 2];
    __shared__ float cs[128], ss[128];
    load_tables(cs, ss);
    for (int t = threadIdx.x; t < 64 * NC; t += blockDim.x) {
        int jj = t / NC, c = t % NC;
        size_t base = ((size_t)n * 64 * NC + t) * 2;
        float ar = 0.f, ai = 0.f;
        for (int p = 0; p < nparts; p++) {
            ar += src[p * pstride + base];
            ai += src[p * pstride + base + 1];
        }
        if (wmul) {
            int sgn = jj < 32 ? 0 : 1, jjm = jj & 31;
            const float* wp = wmul + (((size_t)sgn * 32 + jjm) * 32 + c) * 2;
            float wr = wp[0], wi = wp[1];
            float r2 = ar * wr - ai * wi, i2 = ar * wi + ai * wr;
            ar = r2; ai = i2;
        }
        fs[t * 2] = ar; fs[t * 2 + 1] = ai;
    }
    __syncthreads();
    int step = 128 / P;
    int CG = (NC + 3) >> 2;
    for (int t = threadIdx.x; t < 32 * CG; t += blockDim.x) {
        int yl = t / CG, cg = t % CG;
        int y = ybase + yl, c0 = cg * 4;
        float accr[4] = {0, 0, 0, 0}, acci[4] = {0, 0, 0, 0};
        int ys = (y * step) & 127;
        float stwr = cs[ys], stwi = ss[ys];    // e^{+i y step}
        float wr = 1.f, wi = 0.f;
        #pragma unroll 4
        for (int jr = 0; jr < 64; jr++) {
            if (jr == 32) {
                int a = ((P - 32) * y * step) & 127;
                wr = cs[a]; wi = ss[a];
            }
            #pragma unroll
            for (int cc = 0; cc < 4; cc++) {
                if (c0 + cc < NC) {
                    float ar = fs[(jr * NC + c0 + cc) * 2], ai = fs[(jr * NC + c0 + cc) * 2 + 1];
                    accr[cc] += ar * wr - ai * wi;
                    acci[cc] += ar * wi + ai * wr;
                }
            }
            float nwr = wr * stwr - wi * stwi;
            wi = wr * stwi + wi * stwr;
            wr = nwr;
        }
        #pragma unroll
        for (int cc = 0; cc < 4; cc++) {
            if (c0 + cc < NC) {
                rr[(yl * NC + c0 + cc) * 2] = accr[cc];
                rr[(yl * NC + c0 + cc) * 2 + 1] = acci[cc];
            }
        }
    }
    __syncthreads();
    int nyq = ((NC - 1) * 2 == P) ? 1 : 0;
    int cmax = nyq ? NC - 1 : NC;
    int PP = P * P;
    int slots = 8 * P;
    for (int t = threadIdx.x; t < slots; t += blockDim.x) {
        int x = t % P, yg = t / P;
        int yl0 = yg * 4;
        float acc[4];
        #pragma unroll
        for (int yy = 0; yy < 4; yy++) acc[yy] = rr[((yl0 + yy) * NC) * 2];
        int xs_ = (x * step) & 127;
        float stwr = cs[xs_], stwi = ss[xs_];
        float wr = stwr, wi = stwi;            // c = 1
        #pragma unroll 4
        for (int c = 1; c < cmax; c++) {
            #pragma unroll
            for (int yy = 0; yy < 4; yy++) {
                float re = rr[((yl0 + yy) * NC + c) * 2], im = rr[((yl0 + yy) * NC + c) * 2 + 1];
                acc[yy] += 2.f * (re * wr - im * wi);
            }
            float nwr = wr * stwr - wi * stwi;
            wi = wr * stwi + wi * stwr;
            wr = nwr;
        }
        if (nyq) {
            #pragma unroll
            for (int yy = 0; yy < 4; yy++)
                acc[yy] += rr[((yl0 + yy) * NC + NC - 1) * 2] * wr;
        }
        #pragma unroll
        for (int yy = 0; yy < 4; yy++) {
            int p = (ybase + yl0 + yy) * P + x;
            float v = acc[yy];
            if (yadd) v += yadd[(size_t)n * PP + p];
            dst[(size_t)n * PP + p] = v;
        }
    }
}

// -------- K/Q fused (z=0 -> K, z=1 -> Q); recurrences in both stages
__global__ void k_kq(const float* __restrict__ F2src,
                     const float* __restrict__ wKp, const float* __restrict__ wQp,
                     const float* __restrict__ R64,
                     const float* __restrict__ wsK, const float* __restrict__ bsK,
                     const float* __restrict__ wsQ, const float* __restrict__ bsQ,
                     float* __restrict__ dstK, float* __restrict__ dstQ) {
    int i = blockIdx.x, o = blockIdx.y, z = blockIdx.z;
    const float* w = z ? wQp : wKp;
    const float* ws = z ? wsQ : wsK;
    const float* bs = z ? bsQ : bsK;
    float* dst = z ? dstQ : dstK;
    __shared__ float fw[32 * 16 * 2];
    __shared__ float rr[64 * 16 * 2];
    __shared__ float cs[128], ss[128];
    load_tables(cs, ss);
    for (int t = threadIdx.x; t < 512; t += blockDim.x) {
        int jj = t >> 4, c = t & 15;
        int jr = jj < 16 ? jj : jj + 32;
        int sgn = jj < 16 ? 0 : 1, jjm = jj & 15;
        float ar = F2src[((size_t)(i * 64 + jr) * 33 + c) * 2];
        float ai = F2src[((size_t)(i * 64 + jr) * 33 + c) * 2 + 1];
        const float* wp = w + (((size_t)(sgn * 32 + o) * 16 + jjm) * 16 + c) * 2;
        float wr = wp[0], wi = wp[1];
        fw[t * 2]     = ar * wr - ai * wi;
        fw[t * 2 + 1] = ar * wi + ai * wr;
    }
    __syncthreads();
    for (int t = threadIdx.x; t < 1024; t += blockDim.x) {
        int y = t >> 4, c = t & 15;
        float re = 0.f, im = 0.f;
        int ys = (y * 2) & 127;
        float stwr = cs[ys], stwi = ss[ys];
        float wr = 1.f, wi = 0.f;
        #pragma unroll
        for (int jj = 0; jj < 32; jj++) {
            if (jj == 16) {
                int a = (48 * y * 2) & 127;
                wr = cs[a]; wi = ss[a];
            }
            float ar = fw[(jj * 16 + c) * 2], ai = fw[(jj * 16 + c) * 2 + 1];
            re += ar * wr - ai * wi;
            im += ar * wi + ai * wr;
            float nwr = wr * stwr - wi * stwi;
            wi = wr * stwi + wi * stwr;
            wr = nwr;
        }
        rr[t * 2] = re; rr[t * 2 + 1] = im;
    }
    __syncthreads();
    float wsv = ws[o], bsv = bs[o];
    size_t obase = (size_t)(i * 32 + o) * 4096;
    for (int t = threadIdx.x; t < 1024; t += blockDim.x) {
        int x = t & 63, yg = t >> 6;
        int y0 = yg * 4;
        float acc[4];
        #pragma unroll
        for (int yy = 0; yy < 4; yy++) acc[yy] = rr[((y0 + yy) * 16) * 2];
        int xs_ = (x * 2) & 127;
        float stwr = cs[xs_], stwi = ss[xs_];
        float wr = stwr, wi = stwi;
        #pragma unroll
        for (int c = 1; c < 16; c++) {
            #pragma unroll
            for (int yy = 0; yy < 4; yy++) {
                float re = rr[((y0 + yy) * 16 + c) * 2], im = rr[((y0 + yy) * 16 + c) * 2 + 1];
                acc[yy] += 2.f * (re * wr - im * wi);
            }
            float nwr = wr * stwr - wi * stwi;
            wi = wr * stwi + wi * stwr;
            wr = nwr;
        }
        #pragma unroll
        for (int yy = 0; yy < 4; yy++) {
            int p = (y0 + yy) * 64 + x;
            dst[obase + p] = acc[yy] + wsv * R64[(size_t)i * 4096 + p] + bsv;
        }
    }
}

// -------- scores partials over d-chunks; grid (64, 8)
__global__ void k_scores_part(const float* __restrict__ q, const float* __restrict__ k,
                              float* __restrict__ scp) {
    int bh = blockIdx.x, b = bh >> 5, h = bh & 31;
    int ch = blockIdx.y;
    int tid = threadIdx.x;
    int ti = tid >> 4, si = tid & 15;
    __shared__ float qs_[32 * 132], ks_[32 * 132];
    float a00 = 0.f, a01 = 0.f, a10 = 0.f, a11 = 0.f;
    for (int kk = ch * 512; kk < ch * 512 + 512; kk += 128) {
        __syncthreads();
        for (int t = tid; t < 4096; t += 256) {
            int row = t >> 7, col = t & 127;
            size_t base = (size_t)((b * 32 + row) * 32 + h) * 4096 + kk + col;
            qs_[row * 132 + col] = q[base];
            ks_[row * 132 + col] = k[base];
        }
        __syncthreads();
        #pragma unroll 4
        for (int j = 0; j < 128; j++) {
            float q0 = qs_[(2 * ti) * 132 + j], q1 = qs_[(2 * ti + 1) * 132 + j];
            float k0 = ks_[(2 * si) * 132 + j], k1 = ks_[(2 * si + 1) * 132 + j];
            a00 += q0 * k0; a01 += q0 * k1; a10 += q1 * k0; a11 += q1 * k1;
        }
    }
    float* sp = scp + ((size_t)ch * 64 + bh) * 1024;
    sp[(2 * ti) * 32 + 2 * si]         = a00;
    sp[(2 * ti) * 32 + 2 * si + 1]     = a01;
    sp[(2 * ti + 1) * 32 + 2 * si]     = a10;
    sp[(2 * ti + 1) * 32 + 2 * si + 1] = a11;
}

// -------- combine partials + softmax; 64 blocks x 1024 thr (warp = row)
__global__ void k_softmax(const float* __restrict__ scp, float* __restrict__ attn) {
    int bh = blockIdx.x, tid = threadIdx.x;
    float v = 0.f;
    #pragma unroll
    for (int c = 0; c < 8; c++) v += scp[((size_t)c * 64 + bh) * 1024 + tid];
    v *= (1.f / 64.f);
    float mx = v;
    for (int o = 16; o > 0; o >>= 1) mx = fmaxf(mx, __shfl_xor_sync(0xffffffffu, mx, o));
    float e = expf(v - mx), sm = e;
    for (int o = 16; o > 0; o >>= 1) sm += __shfl_xor_sync(0xffffffffu, sm, o);
    attn[(size_t)bh * 1024 + tid] = e / sm;
}

// -------- Vhat + SpecVhat
__global__ void k_vhat(const float* __restrict__ F2, const float* __restrict__ wV,
                       const float* __restrict__ wVs, const float* __restrict__ bVs,
                       float* __restrict__ vhat, float* __restrict__ svhat) {
    int i = blockIdx.x, h = blockIdx.y;
    __shared__ float f2s[64 * 33 * 2];
    __shared__ float wv_s[1024];
    for (int t = threadIdx.x; t < 64 * 33 * 2; t += blockDim.x)
        f2s[t] = F2[(size_t)i * (64 * 33 * 2) + t];
    for (int t = threadIdx.x; t < 1024; t += blockDim.x) {
        int sgn = t >> 9;
        wv_s[t] = wV[((size_t)(sgn * 32 + h) * 256) * 2 + (t & 511)];
    }
    __syncthreads();
    float wvsv = wVs[h], bvsv = bVs[h];

    #define OF(JJ, CC, ORR, OII) { int sg_ = (JJ) < 16 ? 0 : 1; int jm_ = (JJ) < 16 ? (JJ) : (JJ) - 48; \
        float fr_ = f2s[((JJ) * 33 + (CC)) * 2], fi_ = f2s[((JJ) * 33 + (CC)) * 2 + 1]; \
        float wr_ = wv_s[sg_ * 512 + (jm_ * 16 + (CC)) * 2], wi_ = wv_s[sg_ * 512 + (jm_ * 16 + (CC)) * 2 + 1]; \
        ORR = fr_ * wr_ - fi_ * wi_; OII = fr_ * wi_ + fi_ * wr_; }

    for (int t = threadIdx.x; t < 2048; t += blockDim.x) {
        int jj = t >> 5, c = t & 31;
        float fr = f2s[(jj * 33 + c) * 2], fi = f2s[(jj * 33 + c) * 2 + 1];
        float vr = wvsv * fr, vi = wvsv * fi;
        if (jj == 0 && c == 0) vr += bvsv;
        if (c >= 1 && c < 16 && (jj < 16 || jj >= 48)) {
            float orr, oii; OF(jj, c, orr, oii);
            vr += orr; vi += oii;
        } else if (c == 0) {
            if (jj == 0) {
                float orr, oii; OF(0, 0, orr, oii); (void)oii;
                vr += orr;
            } else if (jj <= 15) {
                float o1r, o1i, o2r, o2i;
                OF(jj, 0, o1r, o1i); OF(64 - jj, 0, o2r, o2i);
                vr += 0.5f * (o1r + o2r); vi += 0.5f * (o1i - o2i);
            } else if (jj == 16) {
                float orr, oii; OF(48, 0, orr, oii);
                vr += 0.5f * orr; vi -= 0.5f * oii;
            } else if (jj == 48) {
                float orr, oii; OF(48, 0, orr, oii);
                vr += 0.5f * orr; vi += 0.5f * oii;
            } else if (jj >= 49) {
                float o1r, o1i, o2r, o2i;
                OF(jj, 0, o1r, o1i); OF(64 - jj, 0, o2r, o2i);
                vr += 0.5f * (o1r + o2r); vi += 0.5f * (o1i - o2i);
            }
        }
        size_t oo = ((size_t)(i * 32 + h) * 2048 + t) * 2;
        vhat[oo] = vr; vhat[oo + 1] = vi;
    }
    for (int t = threadIdx.x; t < 512; t += blockDim.x) {
        int jm = t >> 4, c = t & 15;
        int jj = jm < 16 ? jm : jm + 32;
        float orr, oii; OF(jj, c, orr, oii);
        size_t oo = ((size_t)(i * 32 + h) * 512 + t) * 2;
        svhat[oo] = orr; svhat[oo + 1] = oii;
    }
    #undef OF
}

// -------- sghat = attn x svhat
__global__ void k_ghat(const float* __restrict__ attn, const float* __restrict__ vin,
                       float* __restrict__ gout, int ncols) {
    int b = blockIdx.x, h = blockIdx.y, c0 = blockIdx.z * 256;
    __shared__ float a_sh[1024];
    __shared__ float vs[32 * 256];
    for (int t = threadIdx.x; t < 1024; t += 256)
        a_sh[t] = attn[(size_t)(b * 32 + h) * 1024 + t];
    for (int t = threadIdx.x; t < 8192; t += 256) {
        int s = t >> 8, c = t & 255;
        vs[t] = vin[(size_t)((b * 32 + s) * 32 + h) * ncols + c0 + c];
    }
    __syncthreads();
    int tq = threadIdx.x >> 5;
    int cg = threadIdx.x & 31;
    float acc[4][8];
    #pragma unroll
    for (int r = 0; r < 4; r++)
        #pragma unroll
        for (int cc = 0; cc < 8; cc++) acc[r][cc] = 0.f;
    for (int s = 0; s < 32; s++) {
        float a0 = a_sh[(tq * 4 + 0) * 32 + s];
        float a1 = a_sh[(tq * 4 + 1) * 32 + s];
        float a2 = a_sh[(tq * 4 + 2) * 32 + s];
        float a3 = a_sh[(tq * 4 + 3) * 32 + s];
        const float* vp = vs + s * 256 + cg * 8;
        #pragma unroll
        for (int cc = 0; cc < 8; cc++) {
            float v = vp[cc];
            acc[0][cc] += a0 * v; acc[1][cc] += a1 * v;
            acc[2][cc] += a2 * v; acc[3][cc] += a3 * v;
        }
    }
    #pragma unroll
    for (int r = 0; r < 4; r++)
        #pragma unroll
        for (int cc = 0; cc < 8; cc++)
            gout[(size_t)((b * 32 + tq * 4 + r) * 32 + h) * ncols + c0 + cg * 8 + cc] = acc[r][cc];
}

// -------- fused (attn x vhat) x wP -> PF partials; grid (b=2, mc=16, hg=8)
__global__ void k_gpf(const float* __restrict__ attn, const float* __restrict__ vhat,
                      const float* __restrict__ wP, float* __restrict__ PFp) {
    int b = blockIdx.x, mc = blockIdx.y, hg = blockIdx.z;
    __shared__ float a_sh[1024];
    __shared__ float vs[8192];
    int tid = threadIdx.x;
    int tq = tid >> 5, mg = tid & 31;
    float accr[4][4], acci[4][4];
    #pragma unroll
    for (int r = 0; r < 4; r++)
        #pragma unroll
        for (int m = 0; m < 4; m++) { accr[r][m] = 0.f; acci[r][m] = 0.f; }
    for (int hh = 0; hh < 4; hh++) {
        int h = hg * 4 + hh;
        __syncthreads();
        for (int t = tid; t < 1024; t += 256)
            a_sh[t] = attn[(size_t)(b * 32 + h) * 1024 + t];
        for (int t = tid; t < 8192; t += 256) {
            int s = t >> 8, c = t & 255;
            vs[t] = vhat[((size_t)((b * 32 + s) * 32 + h) * 2048 + mc * 128) * 2 + c];
        }
        __syncthreads();
        float tr[4][4], ti_[4][4];
        #pragma unroll
        for (int r = 0; r < 4; r++)
            #pragma unroll
            for (int m = 0; m < 4; m++) { tr[r][m] = 0.f; ti_[r][m] = 0.f; }
        #pragma unroll 4
        for (int s = 0; s < 32; s++) {
            float a0 = a_sh[(tq * 4 + 0) * 32 + s];
            float a1 = a_sh[(tq * 4 + 1) * 32 + s];
            float a2 = a_sh[(tq * 4 + 2) * 32 + s];
            float a3 = a_sh[(tq * 4 + 3) * 32 + s];
            const float* vp = vs + s * 256 + mg * 8;
            #pragma unroll
            for (int m = 0; m < 4; m++) {
                float vre = vp[m * 2], vim = vp[m * 2 + 1];
                tr[0][m] += a0 * vre; ti_[0][m] += a0 * vim;
                tr[1][m] += a1 * vre; ti_[1][m] += a1 * vim;
                tr[2][m] += a2 * vre; ti_[2][m] += a2 * vim;
                tr[3][m] += a3 * vre; ti_[3][m] += a3 * vim;
            }
        }
        #pragma unroll
        for (int m = 0; m < 4; m++) {
            int M = mc * 128 + mg * 4 + m;
            int jj = M >> 5, c = M & 31;
            int sgn = jj < 32 ? 0 : 1, jjm = jj & 31;
            const float* wp = wP + (((size_t)(sgn * 32 + h) * 32 + jjm) * 32 + c) * 2;
            float wr = wp[0], wi = wp[1];
            #pragma unroll
            for (int r = 0; r < 4; r++) {
                accr[r][m] += tr[r][m] * wr - ti_[r][m] * wi;
                acci[r][m] += tr[r][m] * wi + ti_[r][m] * wr;
            }
        }
    }
    #pragma unroll
    for (int r = 0; r < 4; r++) {
        int i = b * 32 + tq * 4 + r;
        #pragma unroll
        for (int m = 0; m < 4; m++) {
            int M = mc * 128 + mg * 4 + m;
            size_t o = (size_t)hg * (NI * 4096) + (size_t)i * 4096 + (size_t)M * 2;
            PFp[o] = accr[r][m]; PFp[o + 1] = acci[r][m];
        }
    }
}

// -------- window extras into PF partial slot 0
__global__ void k_pfw(const float* __restrict__ sghat, const float* __restrict__ wPs,
                      float* __restrict__ PFp) {
    int i = blockIdx.x;
    int w = blockIdx.y * 256 + threadIdx.x;
    __shared__ float wps_[32];
    if (threadIdx.x < 32) wps_[threadIdx.x] = wPs[threadIdx.x];
    __syncthreads();
    int jm = w >> 4, c = w & 15;
    int jj = jm < 16 ? jm : jm + 32;
    int t = jj * 32 + c;
    float re = 0.f, im = 0.f;
    #pragma unroll 4
    for (int h = 0; h < 32; h++) {
        const float* sg = sghat + ((size_t)(i * 32 + h) * 512 + w) * 2;
        re += wps_[h] * sg[0]; im += wps_[h] * sg[1];
    }
    size_t o = (size_t)i * 4096 + (size_t)t * 2;
    PFp[o] += re; PFp[o + 1] += im;
}

// -------- token mix y2
__global__ void k_tokmix(const float* __restrict__ attn, const float* __restrict__ xan,
                         const float* __restrict__ wPs, const float* __restrict__ wVs,
                         const float* __restrict__ bVs, const float* __restrict__ bPs,
                         float* __restrict__ y2) {
    int b = blockIdx.x;
    int pbase = blockIdx.y * 256;
    int tid = threadIdx.x;
    __shared__ float C[1024];
    __shared__ float xs[32 * 256];
    __shared__ float cb_s;
    {
        int t = tid >> 3, s0 = (tid & 7) * 4;
        float c0 = 0.f, c1 = 0.f, c2 = 0.f, c3 = 0.f;
        for (int h = 0; h < 32; h++) {
            float w = wPs[h] * wVs[h];
            const float* ap = attn + (size_t)(b * 32 + h) * 1024 + t * 32 + s0;
            c0 += w * ap[0]; c1 += w * ap[1]; c2 += w * ap[2]; c3 += w * ap[3];
        }
        C[t * 32 + s0] = c0; C[t * 32 + s0 + 1] = c1;
        C[t * 32 + s0 + 2] = c2; C[t * 32 + s0 + 3] = c3;
    }
    if (tid == 0) {
        float cb = bPs[0];
        for (int h = 0; h < 32; h++) cb += wPs[h] * bVs[h];
        cb_s = cb;
    }
    for (int t = tid; t < 8192; t += 256) {
        int s = t >> 8, c = t & 255;
        xs[t] = xan[(size_t)(b * 32 + s) * HW + pbase + c];
    }
    __syncthreads();
    int t = tid >> 3, pg = tid & 7;
    float acc[32];
    #pragma unroll
    for (int pp = 0; pp < 32; pp++) acc[pp] = 0.f;
    for (int s = 0; s < 32; s++) {
        float cc = C[t * 32 + s];
        const float* xp = xs + s * 256 + pg * 32;
        #pragma unroll
        for (int pp = 0; pp < 32; pp++) acc[pp] += cc * xp[pp];
    }
    float cb = cb_s;
    #pragma unroll
    for (int pp = 0; pp < 32; pp++)
        y2[(size_t)(b * 32 + t) * HW + pbase + pg * 32 + pp] = acc[pp] + cb;
}

extern "C" void kernel_launch(void* const* d_in, const int* in_sizes, int n_in,
                              void* d_out, int out_size) {
    const float* x    = (const float*)d_in[0];
    const float* wK   = (const float*)d_in[1];
    const float* wKs  = (const float*)d_in[2];
    const float* bKs  = (const float*)d_in[3];
    const float* wQ   = (const float*)d_in[4];
    const float* wQs  = (const float*)d_in[5];
    const float* bQs  = (const float*)d_in[6];
    const float* wV   = (const float*)d_in[7];
    const float* wVs  = (const float*)d_in[8];
    const float* bVs  = (const float*)d_in[9];
    const float* wP   = (const float*)d_in[10];
    const float* wPs  = (const float*)d_in[11];
    const float* bPs  = (const float*)d_in[12];
    const float* wM0  = (const float*)d_in[13];
    const float* wM0s = (const float*)d_in[14];
    const float* bM0s = (const float*)d_in[15];
    const float* wM1  = (const float*)d_in[16];
    const float* wM1s = (const float*)d_in[17];
    const float* bM1s = (const float*)d_in[18];
    const float* ng   = (const float*)d_in[19];
    const float* nb   = (const float*)d_in[20];
    float* out = (float*)d_out;

    float *p_xan, *p_F1, *p_F2, *p_R64, *p_k, *p_q, *p_scp, *p_attn;
    float *p_vhat, *p_svhat, *p_sghat, *p_PFp, *p_y2;
    float *p_fno, *p_att, *p_an, *p_m, *p_MF1, *p_MF2;
    cudaGetSymbolAddress((void**)&p_xan,   s_xan);
    cudaGetSymbolAddress((void**)&p_F1,    s_F1);
    cudaGetSymbolAddress((void**)&p_F2,    s_F2);
    cudaGetSymbolAddress((void**)&p_R64,   s_R64);
    cudaGetSymbolAddress((void**)&p_k,     s_k);
    cudaGetSymbolAddress((void**)&p_q,     s_q);
    cudaGetSymbolAddress((void**)&p_scp,   s_scp);
    cudaGetSymbolAddress((void**)&p_attn,  s_attn);
    cudaGetSymbolAddress((void**)&p_vhat,  s_vhat);
    cudaGetSymbolAddress((void**)&p_svhat, s_svhat);
    cudaGetSymbolAddress((void**)&p_sghat, s_sghat);
    cudaGetSymbolAddress((void**)&p_PFp,   s_PFp);
    cudaGetSymbolAddress((void**)&p_y2,    s_y2);
    cudaGetSymbolAddress((void**)&p_fno,   s_fno);
    cudaGetSymbolAddress((void**)&p_att,   s_att);
    cudaGetSymbolAddress((void**)&p_an,    s_an);
    cudaGetSymbolAddress((void**)&p_m,     s_m);
    cudaGetSymbolAddress((void**)&p_MF1,   s_MF1);
    cudaGetSymbolAddress((void**)&p_MF2,   s_MF2);

    const size_t PSTRIDE = (size_t)NI * 4096;

    k_init<<<1, 128>>>();

    // xa_n (idx0) + partial spectrum
    k_inorm<<<NI, 1024>>>(x, nullptr, p_xan, ng, nb, 0, nullptr);
    k_fwd1<33><<<dim3(NI, 4), 264>>>(p_xan, p_F1);
    k_fwd2<<<dim3(NI, 4), 576>>>(p_F1, p_F2, 33);

    // resampled xa_n 64x64
    k_inv2<<<dim3(NI, 2), 512>>>(p_F2, nullptr, p_R64, 33, 64, nullptr, 1, 0);

    // K + Q fused
    k_kq<<<dim3(NI, NH, 2), 256>>>(p_F2, wK, wQ, p_R64, wKs, bKs, wQs, bQs, p_k, p_q);

    // attention weights (split-d partials + softmax)
    k_scores_part<<<dim3(64, 8), 256>>>(p_q, p_k, p_scp);
    k_softmax<<<64, 1024>>>(p_scp, p_attn);

    // mode-space V / attention / projection
    k_vhat<<<dim3(NI, NH), 256>>>(p_F2, wV, wVs, bVs, p_vhat, p_svhat);
    k_ghat<<<dim3(2, 32, 4), 256>>>(p_attn, p_svhat, p_sghat, 1024);
    k_gpf<<<dim3(2, 16, 8), 256>>>(p_attn, p_vhat, wP, p_PFp);
    k_pfw<<<dim3(NI, 2), 256>>>(p_sghat, wPs, p_PFp);
    k_tokmix<<<dim3(2, 64), 256>>>(p_attn, p_xan, wPs, wVs, bVs, bPs, p_y2);
    k_inv2<<<dim3(NI, 4), 512>>>(p_PFp, nullptr, p_fno, 32, 128, p_y2, 8, PSTRIDE);

    // att = IN1(projd + xa); an = IN2(att)
    k_norm12<<<NI, 1024>>>(p_fno, x, p_att, p_an, ng, nb);

    // mixer layer 0 (idx3 + gelu)
    k_fwd1<32><<<dim3(NI, 4), 256>>>(p_an, p_MF1);
    k_fwd2<<<dim3(NI, 4), 512>>>(p_MF1, p_MF2, 32);
    k_inv2<<<dim3(NI, 4), 512>>>(p_MF2, wM0, p_fno, 32, 128, nullptr, 1, 0);
    k_normeps<<<NI, 1024>>>(p_fno, p_an, p_m, ng, nb, 3, wM0s, bM0s, 1);

    // mixer layer 1 (idx4)
    k_fwd1<32><<<dim3(NI, 4), 256>>>(p_m, p_MF1);
    k_fwd2<<<dim3(NI, 4), 512>>>(p_MF1, p_MF2, 32);
    k_inv2<<<dim3(NI, 4), 512>>>(p_MF2, wM1, p_fno, 32, 128, nullptr, 1, 0);
    k_normeps<<<NI, 1024>>>(p_fno, p_m, p_m, ng, nb, 4, wM1s, bM1s, 0);

    // output = IN5(m) + att
    k_inorm<<<NI, 1024>>>(p_m, nullptr, out, ng, nb, 5, p_att);
}